// round 2
// baseline (speedup 1.0000x reference)
#include <cuda_runtime.h>
#include <cuda_bf16.h>
#include <math.h>

// Problem constants: B=4, S=2048, D=1024, H=16, hs=64
#define BATCH 4
#define SEQ   2048
#define DIM   1024
#define HEADS 16
#define HS    64
#define W3    3072   // 3*DIM

typedef unsigned long long u64;

// Packed fp32x2 helpers (sm_103a FFMA2 — not emitted by ptxas from C++)
__device__ __forceinline__ u64 bcast2(float x) {
    u64 r;
    asm("mov.b64 %0, {%1, %1};" : "=l"(r) : "f"(x));
    return r;
}
__device__ __forceinline__ void ffma2(u64& d, u64 a, u64 b) {
    asm("fma.rn.f32x2 %0, %1, %2, %0;" : "+l"(d) : "l"(a), "l"(b));
}
__device__ __forceinline__ float2 unpack2(u64 v) {
    float2 r;
    asm("mov.b64 {%0, %1}, %2;" : "=f"(r.x), "=f"(r.y) : "l"(v));
    return r;
}

// Scratch (device globals; allocation at module load, not runtime)
__device__ float g_qkv[(size_t)BATCH * SEQ * W3];   // [B,S,3D]
__device__ float g_ctx[(size_t)BATCH * SEQ * DIM];  // [B,S,D]

// ---------------------------------------------------------------------------
// SGEMM: C[M,N] = A[M,K] @ B[K,N] + bias[N]   (row-major, M,N % 128 == 0,
// K % 16 == 0). 128x128 tile, BK=16, 256 threads, 8x8 per-thread microtile,
// inner product via packed f32x2 FMA.
// ---------------------------------------------------------------------------
__global__ void __launch_bounds__(256) sgemm_bias_kernel(
    const float* __restrict__ A, const float* __restrict__ B,
    const float* __restrict__ bias, float* __restrict__ C,
    int M, int N, int K)
{
    __shared__ float As[16][132];  // transposed: As[k][m]
    __shared__ float Bs[16][128];  // natural:    Bs[k][n]

    const int tid = threadIdx.x;
    const int tx = tid & 15;       // 0..15 -> N direction
    const int ty = tid >> 4;       // 0..15 -> M direction
    const int bm = blockIdx.y * 128;
    const int bn = blockIdx.x * 128;

    u64 acc[8][4];                 // [i][j2], each holds cols (2*j2, 2*j2+1)
#pragma unroll
    for (int i = 0; i < 8; i++)
#pragma unroll
        for (int j = 0; j < 4; j++) acc[i][j] = 0ULL;   // two packed 0.0f

    for (int k0 = 0; k0 < K; k0 += 16) {
#pragma unroll
        for (int t = 0; t < 2; t++) {
            int i = tid + t * 256;           // 0..511
            // A tile: 128 rows x 4 float4
            int r  = i >> 2;
            int c4 = i & 3;
            float4 a = *(const float4*)(A + (size_t)(bm + r) * K + k0 + c4 * 4);
            As[c4 * 4 + 0][r] = a.x;
            As[c4 * 4 + 1][r] = a.y;
            As[c4 * 4 + 2][r] = a.z;
            As[c4 * 4 + 3][r] = a.w;
            // B tile: 16 rows x 32 float4
            int rb  = i >> 5;
            int cb4 = i & 31;
            *(float4*)&Bs[rb][cb4 * 4] =
                *(const float4*)(B + (size_t)(k0 + rb) * N + bn + cb4 * 4);
        }
        __syncthreads();

#pragma unroll
        for (int k = 0; k < 16; k++) {
            float ar[8];
            *(float4*)(ar)     = *(float4*)&As[k][ty * 8];
            *(float4*)(ar + 4) = *(float4*)&As[k][ty * 8 + 4];
            union { float4 f; u64 u[2]; } b0, b1;
            b0.f = *(float4*)&Bs[k][tx * 8];
            b1.f = *(float4*)&Bs[k][tx * 8 + 4];
            u64 br[4] = {b0.u[0], b0.u[1], b1.u[0], b1.u[1]};
#pragma unroll
            for (int i = 0; i < 8; i++) {
                u64 a2 = bcast2(ar[i]);
#pragma unroll
                for (int j = 0; j < 4; j++)
                    ffma2(acc[i][j], a2, br[j]);
            }
        }
        __syncthreads();
    }

    // epilogue: add bias, store
#pragma unroll
    for (int i = 0; i < 8; i++) {
        int row = bm + ty * 8 + i;
#pragma unroll
        for (int j4 = 0; j4 < 2; j4++) {
            int col = bn + tx * 8 + j4 * 4;
            float2 v0 = unpack2(acc[i][j4 * 2 + 0]);
            float2 v1 = unpack2(acc[i][j4 * 2 + 1]);
            float4 o;
            o.x = v0.x + bias[col + 0];
            o.y = v0.y + bias[col + 1];
            o.z = v1.x + bias[col + 2];
            o.w = v1.y + bias[col + 3];
            *(float4*)(C + (size_t)row * N + col) = o;
        }
    }
}

// ---------------------------------------------------------------------------
// Flash attention (fp32, causal). One block = (b,h, 64-query tile).
// 256 threads: tx (0..15) -> 4 key cols, ty (0..15) -> 4 query rows.
// QK^T and P@V inner products use packed f32x2 FMA.
// ---------------------------------------------------------------------------
__global__ void __launch_bounds__(256) attn_kernel(
    const float* __restrict__ qkv, float* __restrict__ ctx)
{
    extern __shared__ float sm[];
    float (*Qt)[68] = (float(*)[68])(sm);                 // [c][qrow]
    float (*Kt)[68] = (float(*)[68])(sm + 64 * 68);       // [c][krow]
    float (*Vs)[68] = (float(*)[68])(sm + 2 * 64 * 68);   // [krow][c]
    float (*Ps)[68] = (float(*)[68])(sm + 3 * 64 * 68);   // [qrow][krow]

    const int qt = blockIdx.x;          // 0..31
    const int bh = blockIdx.y;          // 0..63
    const int b = bh >> 4;
    const int h = bh & 15;

    const float* base = qkv + (size_t)b * SEQ * W3;
    const int qoff = h * HS;
    const int koff = DIM + h * HS;
    const int voff = 2 * DIM + h * HS;

    const int tid = threadIdx.x;
    const int tx = tid & 15;
    const int ty = tid >> 4;
    const int lr = tid >> 2;     // 0..63 (row for cooperative loads)
    const int lc = tid & 3;      // 0..3  (float4-column for loads)

    // ---- load Q tile transposed: Qt[c][qrow] ----
#pragma unroll
    for (int it = 0; it < 4; it++) {
        int c4 = lc + it * 4;
        float4 v = *(const float4*)(base + (size_t)(qt * 64 + lr) * W3 + qoff + c4 * 4);
        Qt[c4 * 4 + 0][lr] = v.x;
        Qt[c4 * 4 + 1][lr] = v.y;
        Qt[c4 * 4 + 2][lr] = v.z;
        Qt[c4 * 4 + 3][lr] = v.w;
    }

    float m[4], l[4];
    u64 O2[4][2];
#pragma unroll
    for (int i = 0; i < 4; i++) {
        m[i] = -1e30f;
        l[i] = 0.0f;
        O2[i][0] = 0ULL;
        O2[i][1] = 0ULL;
    }

    for (int kt = 0; kt <= qt; kt++) {
        // ---- load K tile transposed + V tile natural ----
#pragma unroll
        for (int it = 0; it < 4; it++) {
            int c4 = lc + it * 4;
            const float* krow = base + (size_t)(kt * 64 + lr) * W3;
            float4 kv = *(const float4*)(krow + koff + c4 * 4);
            Kt[c4 * 4 + 0][lr] = kv.x;
            Kt[c4 * 4 + 1][lr] = kv.y;
            Kt[c4 * 4 + 2][lr] = kv.z;
            Kt[c4 * 4 + 3][lr] = kv.w;
            float4 vv = *(const float4*)(krow + voff + c4 * 4);
            *(float4*)&Vs[lr][c4 * 4] = vv;
        }
        __syncthreads();

        // ---- S = Q K^T (4x4 per thread, packed along key dim) ----
        u64 s2[4][2];
#pragma unroll
        for (int i = 0; i < 4; i++) { s2[i][0] = 0ULL; s2[i][1] = 0ULL; }

#pragma unroll
        for (int c = 0; c < 64; c++) {
            float4 qv = *(float4*)&Qt[c][ty * 4];
            union { float4 f; u64 u[2]; } kv;
            kv.f = *(float4*)&Kt[c][tx * 4];
            float qa[4] = {qv.x, qv.y, qv.z, qv.w};
#pragma unroll
            for (int i = 0; i < 4; i++) {
                u64 q2 = bcast2(qa[i]);
                ffma2(s2[i][0], q2, kv.u[0]);
                ffma2(s2[i][1], q2, kv.u[1]);
            }
        }

        float s[4][4];
#pragma unroll
        for (int i = 0; i < 4; i++) {
            float2 a = unpack2(s2[i][0]);
            float2 bq = unpack2(s2[i][1]);
            s[i][0] = a.x; s[i][1] = a.y; s[i][2] = bq.x; s[i][3] = bq.y;
        }

        const bool diag = (kt == qt);
#pragma unroll
        for (int i = 0; i < 4; i++) {
#pragma unroll
            for (int j = 0; j < 4; j++) {
                s[i][j] *= 0.125f;   // 1/sqrt(64)
                if (diag && (ty * 4 + i) < (tx * 4 + j)) s[i][j] = -1e30f;
            }
        }

        // ---- online softmax ----
#pragma unroll
        for (int i = 0; i < 4; i++) {
            float rm = fmaxf(fmaxf(s[i][0], s[i][1]), fmaxf(s[i][2], s[i][3]));
#pragma unroll
            for (int off = 1; off < 16; off <<= 1)
                rm = fmaxf(rm, __shfl_xor_sync(0xffffffffu, rm, off));
            float mn = fmaxf(m[i], rm);
            float al = __expf(m[i] - mn);
            float rs = 0.0f;
#pragma unroll
            for (int j = 0; j < 4; j++) {
                s[i][j] = __expf(s[i][j] - mn);
                rs += s[i][j];
            }
#pragma unroll
            for (int off = 1; off < 16; off <<= 1)
                rs += __shfl_xor_sync(0xffffffffu, rs, off);
            l[i] = l[i] * al + rs;
            m[i] = mn;
            u64 al2 = bcast2(al);
            // O *= al  (packed multiply via mul.rn.f32x2)
            asm("mul.rn.f32x2 %0, %0, %1;" : "+l"(O2[i][0]) : "l"(al2));
            asm("mul.rn.f32x2 %0, %0, %1;" : "+l"(O2[i][1]) : "l"(al2));
            float4 p = make_float4(s[i][0], s[i][1], s[i][2], s[i][3]);
            *(float4*)&Ps[ty * 4 + i][tx * 4] = p;
        }
        __syncthreads();

        // ---- O += P @ V (packed along headdim) ----
#pragma unroll
        for (int f = 0; f < 64; f++) {
            union { float4 f4; u64 u[2]; } vv;
            vv.f4 = *(float4*)&Vs[f][tx * 4];
            float p0 = Ps[ty * 4 + 0][f];
            float p1 = Ps[ty * 4 + 1][f];
            float p2 = Ps[ty * 4 + 2][f];
            float p3 = Ps[ty * 4 + 3][f];
            u64 b0 = bcast2(p0), b1 = bcast2(p1), b2 = bcast2(p2), b3 = bcast2(p3);
            ffma2(O2[0][0], b0, vv.u[0]); ffma2(O2[0][1], b0, vv.u[1]);
            ffma2(O2[1][0], b1, vv.u[0]); ffma2(O2[1][1], b1, vv.u[1]);
            ffma2(O2[2][0], b2, vv.u[0]); ffma2(O2[2][1], b2, vv.u[1]);
            ffma2(O2[3][0], b3, vv.u[0]); ffma2(O2[3][1], b3, vv.u[1]);
        }
        __syncthreads();
    }

    // ---- epilogue: O / l  -> ctx[b, t, h*64 + d] ----
#pragma unroll
    for (int i = 0; i < 4; i++) {
        float inv = 1.0f / l[i];
        int row = qt * 64 + ty * 4 + i;
        float2 o0 = unpack2(O2[i][0]);
        float2 o1 = unpack2(O2[i][1]);
        float4 o = make_float4(o0.x * inv, o0.y * inv, o1.x * inv, o1.y * inv);
        *(float4*)(ctx + ((size_t)b * SEQ + row) * DIM + h * HS + tx * 4) = o;
    }
}

// ---------------------------------------------------------------------------
extern "C" void kernel_launch(void* const* d_in, const int* in_sizes, int n_in,
                              void* d_out, int out_size)
{
    const float* enc    = (const float*)d_in[0];
    const float* w_attn = (const float*)d_in[1];
    const float* b_attn = (const float*)d_in[2];
    const float* w_proj = (const float*)d_in[3];
    const float* b_proj = (const float*)d_in[4];
    float* out = (float*)d_out;

    float* qkv = nullptr;
    float* ctx = nullptr;
    cudaGetSymbolAddress((void**)&qkv, g_qkv);
    cudaGetSymbolAddress((void**)&ctx, g_ctx);

    const int M = BATCH * SEQ;   // 8192

    // QKV GEMM: [8192,1024] @ [1024,3072] + bias
    {
        dim3 grid(W3 / 128, M / 128);
        sgemm_bias_kernel<<<grid, 256>>>(enc, w_attn, b_attn, qkv, M, W3, DIM);
    }

    // Attention
    {
        static const size_t smem = 4 * 64 * 68 * sizeof(float);  // 69632 B
        cudaFuncSetAttribute(attn_kernel,
                             cudaFuncAttributeMaxDynamicSharedMemorySize,
                             (int)smem);
        dim3 grid(SEQ / 64, BATCH * HEADS);
        attn_kernel<<<grid, 256, smem>>>(qkv, ctx);
    }

    // Output projection: [8192,1024] @ [1024,1024] + bias
    {
        dim3 grid(DIM / 128, M / 128);
        sgemm_bias_kernel<<<grid, 256>>>(ctx, w_proj, b_proj, out, M, DIM, DIM);
    }
}

// round 3
// speedup vs baseline: 1.7154x; 1.7154x over previous
#include <cuda_runtime.h>
#include <cuda_bf16.h>
#include <math.h>
#include <stdint.h>

// Problem constants: B=4, S=2048, D=1024, H=16, hs=64
#define BATCH 4
#define SEQ   2048
#define DIM   1024
#define HEADS 16
#define HS    64
#define W3    3072   // 3*DIM

typedef unsigned long long u64;

// Packed fp32x2 helpers (kept for attention kernel)
__device__ __forceinline__ u64 bcast2(float x) {
    u64 r;
    asm("mov.b64 %0, {%1, %1};" : "=l"(r) : "f"(x));
    return r;
}
__device__ __forceinline__ void ffma2(u64& d, u64 a, u64 b) {
    asm("fma.rn.f32x2 %0, %1, %2, %0;" : "+l"(d) : "l"(a), "l"(b));
}
__device__ __forceinline__ float2 unpack2(u64 v) {
    float2 r;
    asm("mov.b64 {%0, %1}, %2;" : "=f"(r.x), "=f"(r.y) : "l"(v));
    return r;
}

// tf32 helpers
__device__ __forceinline__ uint32_t f2tf(float f) {
    uint32_t u;
    asm("cvt.rna.tf32.f32 %0, %1;" : "=r"(u) : "f"(f));
    return u;
}
__device__ __forceinline__ void mma_tf32(float* d, const uint32_t* a, const uint32_t* b) {
    asm("mma.sync.aligned.m16n8k8.row.col.f32.tf32.tf32.f32 "
        "{%0,%1,%2,%3},{%4,%5,%6,%7},{%8,%9},{%0,%1,%2,%3};"
        : "+f"(d[0]), "+f"(d[1]), "+f"(d[2]), "+f"(d[3])
        : "r"(a[0]), "r"(a[1]), "r"(a[2]), "r"(a[3]), "r"(b[0]), "r"(b[1]));
}
__device__ __forceinline__ void ldsm_x4(uint32_t* r, uint32_t addr) {
    asm volatile("ldmatrix.sync.aligned.m8n8.x4.shared.b16 {%0,%1,%2,%3}, [%4];"
                 : "=r"(r[0]), "=r"(r[1]), "=r"(r[2]), "=r"(r[3]) : "r"(addr));
}

// Scratch (device globals; allocation at module load, not runtime)
__device__ float g_qkv[(size_t)BATCH * SEQ * W3];   // [B,S,3D]
__device__ float g_ctx[(size_t)BATCH * SEQ * DIM];  // [B,S,D]

// ---------------------------------------------------------------------------
// tf32 tensor-core GEMM: C[M,N] = A[M,K] @ B[K,N] + bias[N]
// Row-major. M,N % 128 == 0, K % 32 == 0.
// CTA: 128x128x32, 256 threads = 8 warps in 2(M) x 4(N); warp tile 64x32.
// mma.sync.m16n8k8.tf32; A frags via ldmatrix.x4, B frags via scalar LDS.
// ---------------------------------------------------------------------------
#define GBM 128
#define GBN 128
#define GBK 32
#define AS_STRIDE 36   // words; conflict-free for LDSM (16B groups: 9r mod 8 distinct)
#define BS_STRIDE 136  // words; conflict-free for b-frag LDS (k stride = 8 banks)

__global__ void __launch_bounds__(256) tf32_gemm_bias(
    const float* __restrict__ A, const float* __restrict__ B,
    const float* __restrict__ bias, float* __restrict__ C,
    int M, int N, int K)
{
    __shared__ uint32_t As[GBM * AS_STRIDE];   // [m][k] natural, tf32 bits
    __shared__ uint32_t Bs[GBK * BS_STRIDE];   // [k][n] natural, tf32 bits

    const int tid  = threadIdx.x;
    const int lane = tid & 31;
    const int warp = tid >> 5;
    const int wm = warp >> 2;      // 0..1  -> 64 rows each
    const int wn = warp & 3;       // 0..3  -> 32 cols each
    const int g  = lane >> 2;      // 0..7
    const int tg = lane & 3;       // 0..3

    const int bm = blockIdx.y * GBM;
    const int bn = blockIdx.x * GBN;

    float acc[4][4][4];            // [mt][nt][c]
#pragma unroll
    for (int mt = 0; mt < 4; mt++)
#pragma unroll
        for (int nt = 0; nt < 4; nt++)
#pragma unroll
            for (int c = 0; c < 4; c++) acc[mt][nt][c] = 0.0f;

    // LDSM per-lane address: row = wm*64 + mt*16 + (lane&15), col half = lane>>4
    const int a_row  = wm * 64 + (lane & 15);
    const int a_half = (lane >> 4) * 4;     // 0 or 4 (f32 col offset)
    const uint32_t as_base =
        (uint32_t)__cvta_generic_to_shared(&As[0]) +
        (uint32_t)((a_row * AS_STRIDE + a_half) * 4);

    for (int k0 = 0; k0 < K; k0 += GBK) {
        // ---- load A tile 128x32 (coalesced), convert to tf32, STS.128 ----
#pragma unroll
        for (int t = 0; t < 4; t++) {
            int i  = tid + t * 256;        // 0..1023
            int r  = i >> 3;               // 0..127
            int c4 = i & 7;                // 0..7
            float4 v = *(const float4*)(A + (size_t)(bm + r) * K + k0 + c4 * 4);
            uint4 u;
            u.x = f2tf(v.x); u.y = f2tf(v.y); u.z = f2tf(v.z); u.w = f2tf(v.w);
            *(uint4*)&As[r * AS_STRIDE + c4 * 4] = u;
        }
        // ---- load B tile 32x128 (coalesced), convert, STS.128 ----
#pragma unroll
        for (int t = 0; t < 4; t++) {
            int i   = tid + t * 256;
            int kr  = i >> 5;              // 0..31
            int nc4 = i & 31;              // 0..31
            float4 v = *(const float4*)(B + (size_t)(k0 + kr) * N + bn + nc4 * 4);
            uint4 u;
            u.x = f2tf(v.x); u.y = f2tf(v.y); u.z = f2tf(v.z); u.w = f2tf(v.w);
            *(uint4*)&Bs[kr * BS_STRIDE + nc4 * 4] = u;
        }
        __syncthreads();

#pragma unroll
        for (int ks = 0; ks < 4; ks++) {
            uint32_t afr[4][4];
#pragma unroll
            for (int mt = 0; mt < 4; mt++) {
                uint32_t addr = as_base + (uint32_t)((mt * 16 * AS_STRIDE + ks * 8) * 4);
                ldsm_x4(afr[mt], addr);
            }
            uint32_t bfr[4][2];
#pragma unroll
            for (int nt = 0; nt < 4; nt++) {
                int n = wn * 32 + nt * 8 + g;
                bfr[nt][0] = Bs[(ks * 8 + tg) * BS_STRIDE + n];
                bfr[nt][1] = Bs[(ks * 8 + tg + 4) * BS_STRIDE + n];
            }
#pragma unroll
            for (int mt = 0; mt < 4; mt++)
#pragma unroll
                for (int nt = 0; nt < 4; nt++)
                    mma_tf32(acc[mt][nt], afr[mt], bfr[nt]);
        }
        __syncthreads();
    }

    // ---- epilogue: bias + store ----
#pragma unroll
    for (int mt = 0; mt < 4; mt++) {
#pragma unroll
        for (int nt = 0; nt < 4; nt++) {
            int row = bm + wm * 64 + mt * 16 + g;
            int col = bn + wn * 32 + nt * 8 + 2 * tg;
            float b0 = bias[col], b1 = bias[col + 1];
            float2 o0 = make_float2(acc[mt][nt][0] + b0, acc[mt][nt][1] + b1);
            float2 o1 = make_float2(acc[mt][nt][2] + b0, acc[mt][nt][3] + b1);
            *(float2*)(C + (size_t)row * N + col)       = o0;
            *(float2*)(C + (size_t)(row + 8) * N + col) = o1;
        }
    }
}

// ---------------------------------------------------------------------------
// Flash attention (fp32, causal). One block = (b,h, 64-query tile).
// ---------------------------------------------------------------------------
__global__ void __launch_bounds__(256) attn_kernel(
    const float* __restrict__ qkv, float* __restrict__ ctx)
{
    extern __shared__ float sm[];
    float (*Qt)[68] = (float(*)[68])(sm);                 // [c][qrow]
    float (*Kt)[68] = (float(*)[68])(sm + 64 * 68);       // [c][krow]
    float (*Vs)[68] = (float(*)[68])(sm + 2 * 64 * 68);   // [krow][c]
    float (*Ps)[68] = (float(*)[68])(sm + 3 * 64 * 68);   // [qrow][krow]

    const int qt = blockIdx.x;          // 0..31
    const int bh = blockIdx.y;          // 0..63
    const int b = bh >> 4;
    const int h = bh & 15;

    const float* base = qkv + (size_t)b * SEQ * W3;
    const int qoff = h * HS;
    const int koff = DIM + h * HS;
    const int voff = 2 * DIM + h * HS;

    const int tid = threadIdx.x;
    const int tx = tid & 15;
    const int ty = tid >> 4;
    const int lr = tid >> 2;     // 0..63
    const int lc = tid & 3;      // 0..3

#pragma unroll
    for (int it = 0; it < 4; it++) {
        int c4 = lc + it * 4;
        float4 v = *(const float4*)(base + (size_t)(qt * 64 + lr) * W3 + qoff + c4 * 4);
        Qt[c4 * 4 + 0][lr] = v.x;
        Qt[c4 * 4 + 1][lr] = v.y;
        Qt[c4 * 4 + 2][lr] = v.z;
        Qt[c4 * 4 + 3][lr] = v.w;
    }

    float m[4], l[4];
    u64 O2[4][2];
#pragma unroll
    for (int i = 0; i < 4; i++) {
        m[i] = -1e30f;
        l[i] = 0.0f;
        O2[i][0] = 0ULL;
        O2[i][1] = 0ULL;
    }

    for (int kt = 0; kt <= qt; kt++) {
#pragma unroll
        for (int it = 0; it < 4; it++) {
            int c4 = lc + it * 4;
            const float* krow = base + (size_t)(kt * 64 + lr) * W3;
            float4 kv = *(const float4*)(krow + koff + c4 * 4);
            Kt[c4 * 4 + 0][lr] = kv.x;
            Kt[c4 * 4 + 1][lr] = kv.y;
            Kt[c4 * 4 + 2][lr] = kv.z;
            Kt[c4 * 4 + 3][lr] = kv.w;
            float4 vv = *(const float4*)(krow + voff + c4 * 4);
            *(float4*)&Vs[lr][c4 * 4] = vv;
        }
        __syncthreads();

        u64 s2[4][2];
#pragma unroll
        for (int i = 0; i < 4; i++) { s2[i][0] = 0ULL; s2[i][1] = 0ULL; }

#pragma unroll
        for (int c = 0; c < 64; c++) {
            float4 qv = *(float4*)&Qt[c][ty * 4];
            union { float4 f; u64 u[2]; } kv;
            kv.f = *(float4*)&Kt[c][tx * 4];
            float qa[4] = {qv.x, qv.y, qv.z, qv.w};
#pragma unroll
            for (int i = 0; i < 4; i++) {
                u64 q2 = bcast2(qa[i]);
                ffma2(s2[i][0], q2, kv.u[0]);
                ffma2(s2[i][1], q2, kv.u[1]);
            }
        }

        float s[4][4];
#pragma unroll
        for (int i = 0; i < 4; i++) {
            float2 a = unpack2(s2[i][0]);
            float2 bq = unpack2(s2[i][1]);
            s[i][0] = a.x; s[i][1] = a.y; s[i][2] = bq.x; s[i][3] = bq.y;
        }

        const bool diag = (kt == qt);
#pragma unroll
        for (int i = 0; i < 4; i++) {
#pragma unroll
            for (int j = 0; j < 4; j++) {
                s[i][j] *= 0.125f;
                if (diag && (ty * 4 + i) < (tx * 4 + j)) s[i][j] = -1e30f;
            }
        }

#pragma unroll
        for (int i = 0; i < 4; i++) {
            float rm = fmaxf(fmaxf(s[i][0], s[i][1]), fmaxf(s[i][2], s[i][3]));
#pragma unroll
            for (int off = 1; off < 16; off <<= 1)
                rm = fmaxf(rm, __shfl_xor_sync(0xffffffffu, rm, off));
            float mn = fmaxf(m[i], rm);
            float al = __expf(m[i] - mn);
            float rs = 0.0f;
#pragma unroll
            for (int j = 0; j < 4; j++) {
                s[i][j] = __expf(s[i][j] - mn);
                rs += s[i][j];
            }
#pragma unroll
            for (int off = 1; off < 16; off <<= 1)
                rs += __shfl_xor_sync(0xffffffffu, rs, off);
            l[i] = l[i] * al + rs;
            m[i] = mn;
            u64 al2 = bcast2(al);
            asm("mul.rn.f32x2 %0, %0, %1;" : "+l"(O2[i][0]) : "l"(al2));
            asm("mul.rn.f32x2 %0, %0, %1;" : "+l"(O2[i][1]) : "l"(al2));
            float4 p = make_float4(s[i][0], s[i][1], s[i][2], s[i][3]);
            *(float4*)&Ps[ty * 4 + i][tx * 4] = p;
        }
        __syncthreads();

#pragma unroll
        for (int f = 0; f < 64; f++) {
            union { float4 f4; u64 u[2]; } vv;
            vv.f4 = *(float4*)&Vs[f][tx * 4];
            float p0 = Ps[ty * 4 + 0][f];
            float p1 = Ps[ty * 4 + 1][f];
            float p2 = Ps[ty * 4 + 2][f];
            float p3 = Ps[ty * 4 + 3][f];
            u64 b0 = bcast2(p0), b1 = bcast2(p1), b2 = bcast2(p2), b3 = bcast2(p3);
            ffma2(O2[0][0], b0, vv.u[0]); ffma2(O2[0][1], b0, vv.u[1]);
            ffma2(O2[1][0], b1, vv.u[0]); ffma2(O2[1][1], b1, vv.u[1]);
            ffma2(O2[2][0], b2, vv.u[0]); ffma2(O2[2][1], b2, vv.u[1]);
            ffma2(O2[3][0], b3, vv.u[0]); ffma2(O2[3][1], b3, vv.u[1]);
        }
        __syncthreads();
    }

#pragma unroll
    for (int i = 0; i < 4; i++) {
        float inv = 1.0f / l[i];
        int row = qt * 64 + ty * 4 + i;
        float2 o0 = unpack2(O2[i][0]);
        float2 o1 = unpack2(O2[i][1]);
        float4 o = make_float4(o0.x * inv, o0.y * inv, o1.x * inv, o1.y * inv);
        *(float4*)(ctx + ((size_t)b * SEQ + row) * DIM + h * HS + tx * 4) = o;
    }
}

// ---------------------------------------------------------------------------
extern "C" void kernel_launch(void* const* d_in, const int* in_sizes, int n_in,
                              void* d_out, int out_size)
{
    const float* enc    = (const float*)d_in[0];
    const float* w_attn = (const float*)d_in[1];
    const float* b_attn = (const float*)d_in[2];
    const float* w_proj = (const float*)d_in[3];
    const float* b_proj = (const float*)d_in[4];
    float* out = (float*)d_out;

    float* qkv = nullptr;
    float* ctx = nullptr;
    cudaGetSymbolAddress((void**)&qkv, g_qkv);
    cudaGetSymbolAddress((void**)&ctx, g_ctx);

    const int M = BATCH * SEQ;   // 8192

    // QKV GEMM: [8192,1024] @ [1024,3072] + bias  (tf32 tensor cores)
    {
        dim3 grid(W3 / GBN, M / GBM);
        tf32_gemm_bias<<<grid, 256>>>(enc, w_attn, b_attn, qkv, M, W3, DIM);
    }

    // Attention (fp32 flash)
    {
        static const size_t smem = 4 * 64 * 68 * sizeof(float);  // 69632 B
        cudaFuncSetAttribute(attn_kernel,
                             cudaFuncAttributeMaxDynamicSharedMemorySize,
                             (int)smem);
        dim3 grid(SEQ / 64, BATCH * HEADS);
        attn_kernel<<<grid, 256, smem>>>(qkv, ctx);
    }

    // Output projection: [8192,1024] @ [1024,1024] + bias  (tf32 tensor cores)
    {
        dim3 grid(DIM / GBN, M / GBM);
        tf32_gemm_bias<<<grid, 256>>>(ctx, w_proj, b_proj, out, M, DIM, DIM);
    }
}

// round 4
// speedup vs baseline: 3.3340x; 1.9436x over previous
#include <cuda_runtime.h>
#include <cuda_bf16.h>
#include <math.h>
#include <stdint.h>

// Problem constants: B=4, S=2048, D=1024, H=16, hs=64
#define BATCH 4
#define SEQ   2048
#define DIM   1024
#define HEADS 16
#define HS    64
#define W3    3072   // 3*DIM

// tf32 helpers
__device__ __forceinline__ uint32_t f2tf(float f) {
    uint32_t u;
    asm("cvt.rna.tf32.f32 %0, %1;" : "=r"(u) : "f"(f));
    return u;
}
__device__ __forceinline__ void mma_tf32(float* d, const uint32_t* a, const uint32_t* b) {
    asm("mma.sync.aligned.m16n8k8.row.col.f32.tf32.tf32.f32 "
        "{%0,%1,%2,%3},{%4,%5,%6,%7},{%8,%9},{%0,%1,%2,%3};"
        : "+f"(d[0]), "+f"(d[1]), "+f"(d[2]), "+f"(d[3])
        : "r"(a[0]), "r"(a[1]), "r"(a[2]), "r"(a[3]), "r"(b[0]), "r"(b[1]));
}
__device__ __forceinline__ void ldsm_x4(uint32_t* r, uint32_t addr) {
    asm volatile("ldmatrix.sync.aligned.m8n8.x4.shared.b16 {%0,%1,%2,%3}, [%4];"
                 : "=r"(r[0]), "=r"(r[1]), "=r"(r[2]), "=r"(r[3]) : "r"(addr));
}

// Scratch (device globals)
__device__ float g_qkv[(size_t)BATCH * SEQ * W3];   // [B,S,3D]
__device__ float g_ctx[(size_t)BATCH * SEQ * DIM];  // [B,S,D]

// ---------------------------------------------------------------------------
// tf32 tensor-core GEMM: C[M,N] = A[M,K] @ B[K,N] + bias[N]  (unchanged R3)
// ---------------------------------------------------------------------------
#define GBM 128
#define GBN 128
#define GBK 32
#define AS_STRIDE 36
#define BS_STRIDE 136

__global__ void __launch_bounds__(256) tf32_gemm_bias(
    const float* __restrict__ A, const float* __restrict__ B,
    const float* __restrict__ bias, float* __restrict__ C,
    int M, int N, int K)
{
    __shared__ uint32_t As[GBM * AS_STRIDE];
    __shared__ uint32_t Bs[GBK * BS_STRIDE];

    const int tid  = threadIdx.x;
    const int lane = tid & 31;
    const int warp = tid >> 5;
    const int wm = warp >> 2;
    const int wn = warp & 3;
    const int g  = lane >> 2;
    const int tg = lane & 3;

    const int bm = blockIdx.y * GBM;
    const int bn = blockIdx.x * GBN;

    float acc[4][4][4];
#pragma unroll
    for (int mt = 0; mt < 4; mt++)
#pragma unroll
        for (int nt = 0; nt < 4; nt++)
#pragma unroll
            for (int c = 0; c < 4; c++) acc[mt][nt][c] = 0.0f;

    const int a_row  = wm * 64 + (lane & 15);
    const int a_half = (lane >> 4) * 4;
    const uint32_t as_base =
        (uint32_t)__cvta_generic_to_shared(&As[0]) +
        (uint32_t)((a_row * AS_STRIDE + a_half) * 4);

    for (int k0 = 0; k0 < K; k0 += GBK) {
#pragma unroll
        for (int t = 0; t < 4; t++) {
            int i  = tid + t * 256;
            int r  = i >> 3;
            int c4 = i & 7;
            float4 v = *(const float4*)(A + (size_t)(bm + r) * K + k0 + c4 * 4);
            uint4 u;
            u.x = f2tf(v.x); u.y = f2tf(v.y); u.z = f2tf(v.z); u.w = f2tf(v.w);
            *(uint4*)&As[r * AS_STRIDE + c4 * 4] = u;
        }
#pragma unroll
        for (int t = 0; t < 4; t++) {
            int i   = tid + t * 256;
            int kr  = i >> 5;
            int nc4 = i & 31;
            float4 v = *(const float4*)(B + (size_t)(k0 + kr) * N + bn + nc4 * 4);
            uint4 u;
            u.x = f2tf(v.x); u.y = f2tf(v.y); u.z = f2tf(v.z); u.w = f2tf(v.w);
            *(uint4*)&Bs[kr * BS_STRIDE + nc4 * 4] = u;
        }
        __syncthreads();

#pragma unroll
        for (int ks = 0; ks < 4; ks++) {
            uint32_t afr[4][4];
#pragma unroll
            for (int mt = 0; mt < 4; mt++) {
                uint32_t addr = as_base + (uint32_t)((mt * 16 * AS_STRIDE + ks * 8) * 4);
                ldsm_x4(afr[mt], addr);
            }
            uint32_t bfr[4][2];
#pragma unroll
            for (int nt = 0; nt < 4; nt++) {
                int n = wn * 32 + nt * 8 + g;
                bfr[nt][0] = Bs[(ks * 8 + tg) * BS_STRIDE + n];
                bfr[nt][1] = Bs[(ks * 8 + tg + 4) * BS_STRIDE + n];
            }
#pragma unroll
            for (int mt = 0; mt < 4; mt++)
#pragma unroll
                for (int nt = 0; nt < 4; nt++)
                    mma_tf32(acc[mt][nt], afr[mt], bfr[nt]);
        }
        __syncthreads();
    }

#pragma unroll
    for (int mt = 0; mt < 4; mt++) {
#pragma unroll
        for (int nt = 0; nt < 4; nt++) {
            int row = bm + wm * 64 + mt * 16 + g;
            int col = bn + wn * 32 + nt * 8 + 2 * tg;
            float b0 = bias[col], b1 = bias[col + 1];
            float2 o0 = make_float2(acc[mt][nt][0] + b0, acc[mt][nt][1] + b1);
            float2 o1 = make_float2(acc[mt][nt][2] + b0, acc[mt][nt][3] + b1);
            *(float2*)(C + (size_t)row * N + col)       = o0;
            *(float2*)(C + (size_t)(row + 8) * N + col) = o1;
        }
    }
}

// ---------------------------------------------------------------------------
// Tensor-core flash attention (tf32, causal).
// Block = (b,h, 128-query tile); 8 warps x 16 query rows; 64-key tiles.
// Q frags live in registers (smem region recycled for P).
// ---------------------------------------------------------------------------
#define BQ 128
#define BK 64
#define QP_STRIDE 68   // words; /4=17 odd -> conflict-free ldsm
#define V_STRIDE  72   // words; scalar b-frag LDS conflict-free (8tg+g)

__global__ void __launch_bounds__(256) attn_tc_kernel(
    const float* __restrict__ qkv, float* __restrict__ ctx)
{
    extern __shared__ uint32_t smu[];
    uint32_t* QPs = smu;                              // [128][68] Q, then P
    uint32_t* Ks  = smu + BQ * QP_STRIDE;             // [64][68]
    uint32_t* Vs  = Ks + BK * QP_STRIDE;              // [64][72]

    const int qt = (int)gridDim.x - 1 - (int)blockIdx.x;   // heavy tiles first
    const int bh = blockIdx.y;
    const int b = bh >> 4, h = bh & 15;
    const int qbase = qt * BQ;

    const float* base = qkv + (size_t)b * SEQ * W3;
    const int qoff = h * HS, koff = DIM + h * HS, voff = 2 * DIM + h * HS;

    const int tid = threadIdx.x, lane = tid & 31, w = tid >> 5;
    const int g = lane >> 2, tg = lane & 3;

    // ---- load Q tile (scaled by 1/8 = exact), convert tf32 ----
#pragma unroll
    for (int it = 0; it < 8; it++) {
        int i = tid + it * 256;
        int r = i >> 4, c4 = i & 15;
        float4 v = *(const float4*)(base + (size_t)(qbase + r) * W3 + qoff + c4 * 4);
        uint4 u;
        u.x = f2tf(v.x * 0.125f); u.y = f2tf(v.y * 0.125f);
        u.z = f2tf(v.z * 0.125f); u.w = f2tf(v.w * 0.125f);
        *(uint4*)&QPs[r * QP_STRIDE + c4 * 4] = u;
    }
    __syncthreads();

    // ---- Q frags -> registers (invariant across key tiles) ----
    const uint32_t qp_base =
        (uint32_t)__cvta_generic_to_shared(QPs) +
        (uint32_t)(((w * 16 + (lane & 15)) * QP_STRIDE + (lane >> 4) * 4) * 4);
    uint32_t qfr[8][4];
#pragma unroll
    for (int ks = 0; ks < 8; ks++)
        ldsm_x4(qfr[ks], qp_base + ks * 32);

    // K ldsm base: lanes 0-7 rows0-7 klow | 8-15 rows0-7 khigh | 16-23 rows8-15 klow | 24-31 khigh
    const uint32_t k_base =
        (uint32_t)__cvta_generic_to_shared(Ks) +
        (uint32_t)(((((lane >> 4) * 8) + (lane & 7)) * QP_STRIDE + ((lane >> 3) & 1) * 4) * 4);

    float m0 = -1e30f, m1 = -1e30f, l0 = 0.0f, l1 = 0.0f;
    float o[8][4];
#pragma unroll
    for (int nt = 0; nt < 8; nt++)
#pragma unroll
        for (int c = 0; c < 4; c++) o[nt][c] = 0.0f;

    const int nkt = 2 * qt + 2;
    const int qr0 = qbase + w * 16 + g;

    for (int kt = 0; kt < nkt; kt++) {
        const int kt0 = kt * BK;
        __syncthreads();   // prev-tile K/V readers done (covers Q ldsm on iter 0)

        // ---- load K,V tile ----
#pragma unroll
        for (int it = 0; it < 4; it++) {
            int i = tid + it * 256;
            int r = i >> 4, c4 = i & 15;
            const float* row = base + (size_t)(kt0 + r) * W3;
            float4 kv = *(const float4*)(row + koff + c4 * 4);
            uint4 uk;
            uk.x = f2tf(kv.x); uk.y = f2tf(kv.y); uk.z = f2tf(kv.z); uk.w = f2tf(kv.w);
            *(uint4*)&Ks[r * QP_STRIDE + c4 * 4] = uk;
            float4 vv = *(const float4*)(row + voff + c4 * 4);
            uint4 uv;
            uv.x = f2tf(vv.x); uv.y = f2tf(vv.y); uv.z = f2tf(vv.z); uv.w = f2tf(vv.w);
            *(uint4*)&Vs[r * V_STRIDE + c4 * 4] = uv;
        }
        __syncthreads();

        // ---- S = (Q/8) K^T ----
        float s[8][4];
#pragma unroll
        for (int nt = 0; nt < 8; nt++)
#pragma unroll
            for (int c = 0; c < 4; c++) s[nt][c] = 0.0f;

#pragma unroll
        for (int ks = 0; ks < 8; ks++) {
#pragma unroll
            for (int ntp = 0; ntp < 4; ntp++) {
                uint32_t bb[4];
                ldsm_x4(bb, k_base + (uint32_t)(ntp * 16 * QP_STRIDE * 4) + ks * 32);
                mma_tf32(s[2 * ntp],     qfr[ks], bb);
                mma_tf32(s[2 * ntp + 1], qfr[ks], bb + 2);
            }
        }

        // ---- causal mask (only last two tiles of the block need it) ----
        if (kt0 + BK > qbase) {
#pragma unroll
            for (int nt = 0; nt < 8; nt++) {
                int kc = kt0 + nt * 8 + 2 * tg;
                if (qr0 < kc)         s[nt][0] = -1e30f;
                if (qr0 < kc + 1)     s[nt][1] = -1e30f;
                if (qr0 + 8 < kc)     s[nt][2] = -1e30f;
                if (qr0 + 8 < kc + 1) s[nt][3] = -1e30f;
            }
        }

        // ---- online softmax (rows g and g+8 of warp band) ----
        float mx0 = -1e30f, mx1 = -1e30f;
#pragma unroll
        for (int nt = 0; nt < 8; nt++) {
            mx0 = fmaxf(mx0, fmaxf(s[nt][0], s[nt][1]));
            mx1 = fmaxf(mx1, fmaxf(s[nt][2], s[nt][3]));
        }
        mx0 = fmaxf(mx0, __shfl_xor_sync(0xffffffffu, mx0, 1));
        mx0 = fmaxf(mx0, __shfl_xor_sync(0xffffffffu, mx0, 2));
        mx1 = fmaxf(mx1, __shfl_xor_sync(0xffffffffu, mx1, 1));
        mx1 = fmaxf(mx1, __shfl_xor_sync(0xffffffffu, mx1, 2));

        float mn0 = fmaxf(m0, mx0), mn1 = fmaxf(m1, mx1);
        float al0 = __expf(m0 - mn0), al1 = __expf(m1 - mn1);
        float sum0 = 0.0f, sum1 = 0.0f;

        const int pr0 = w * 16 + g;
#pragma unroll
        for (int nt = 0; nt < 8; nt++) {
            float p0 = __expf(s[nt][0] - mn0);
            float p1 = __expf(s[nt][1] - mn0);
            float p2 = __expf(s[nt][2] - mn1);
            float p3 = __expf(s[nt][3] - mn1);
            sum0 += p0 + p1;
            sum1 += p2 + p3;
            int col = nt * 8 + 2 * tg;
            QPs[pr0 * QP_STRIDE + col]           = f2tf(p0);
            QPs[pr0 * QP_STRIDE + col + 1]       = f2tf(p1);
            QPs[(pr0 + 8) * QP_STRIDE + col]     = f2tf(p2);
            QPs[(pr0 + 8) * QP_STRIDE + col + 1] = f2tf(p3);
        }
        sum0 += __shfl_xor_sync(0xffffffffu, sum0, 1);
        sum0 += __shfl_xor_sync(0xffffffffu, sum0, 2);
        sum1 += __shfl_xor_sync(0xffffffffu, sum1, 1);
        sum1 += __shfl_xor_sync(0xffffffffu, sum1, 2);

        l0 = l0 * al0 + sum0; m0 = mn0;
        l1 = l1 * al1 + sum1; m1 = mn1;

#pragma unroll
        for (int nt = 0; nt < 8; nt++) {
            o[nt][0] *= al0; o[nt][1] *= al0;
            o[nt][2] *= al1; o[nt][3] *= al1;
        }

        __syncwarp();   // P band visible to own warp's ldmatrix

        // ---- O += P @ V ----
#pragma unroll
        for (int ks2 = 0; ks2 < 8; ks2++) {
            uint32_t pfr[4];
            ldsm_x4(pfr, qp_base + ks2 * 32);
#pragma unroll
            for (int nt = 0; nt < 8; nt++) {
                uint32_t bb[2];
                bb[0] = Vs[(ks2 * 8 + tg) * V_STRIDE + nt * 8 + g];
                bb[1] = Vs[(ks2 * 8 + tg + 4) * V_STRIDE + nt * 8 + g];
                mma_tf32(o[nt], pfr, bb);
            }
        }
    }

    // ---- epilogue ----
    float inv0 = 1.0f / l0, inv1 = 1.0f / l1;
    float* orow0 = ctx + ((size_t)b * SEQ + qr0) * DIM + h * HS;
    float* orow1 = orow0 + (size_t)8 * DIM;
#pragma unroll
    for (int nt = 0; nt < 8; nt++) {
        int col = nt * 8 + 2 * tg;
        *(float2*)(orow0 + col) = make_float2(o[nt][0] * inv0, o[nt][1] * inv0);
        *(float2*)(orow1 + col) = make_float2(o[nt][2] * inv1, o[nt][3] * inv1);
    }
}

// ---------------------------------------------------------------------------
extern "C" void kernel_launch(void* const* d_in, const int* in_sizes, int n_in,
                              void* d_out, int out_size)
{
    const float* enc    = (const float*)d_in[0];
    const float* w_attn = (const float*)d_in[1];
    const float* b_attn = (const float*)d_in[2];
    const float* w_proj = (const float*)d_in[3];
    const float* b_proj = (const float*)d_in[4];
    float* out = (float*)d_out;

    float* qkv = nullptr;
    float* ctx = nullptr;
    cudaGetSymbolAddress((void**)&qkv, g_qkv);
    cudaGetSymbolAddress((void**)&ctx, g_ctx);

    const int M = BATCH * SEQ;   // 8192

    // QKV GEMM (tf32 tensor cores)
    {
        dim3 grid(W3 / GBN, M / GBM);
        tf32_gemm_bias<<<grid, 256>>>(enc, w_attn, b_attn, qkv, M, W3, DIM);
    }

    // Attention (tf32 tensor cores)
    {
        const int smem = (BQ * QP_STRIDE + BK * QP_STRIDE + BK * V_STRIDE) * 4; // 70656
        cudaFuncSetAttribute(attn_tc_kernel,
                             cudaFuncAttributeMaxDynamicSharedMemorySize, smem);
        dim3 grid(SEQ / BQ, BATCH * HEADS);
        attn_tc_kernel<<<grid, 256, smem>>>(qkv, ctx);
    }

    // Output projection (tf32 tensor cores)
    {
        dim3 grid(DIM / GBN, M / GBM);
        tf32_gemm_bias<<<grid, 256>>>(ctx, w_proj, b_proj, out, M, DIM, DIM);
    }
}

// round 5
// speedup vs baseline: 3.4826x; 1.0446x over previous
#include <cuda_runtime.h>
#include <cuda_bf16.h>
#include <math.h>
#include <stdint.h>

// Problem constants: B=4, S=2048, D=1024, H=16, hs=64
#define BATCH 4
#define SEQ   2048
#define DIM   1024
#define HEADS 16
#define HS    64
#define W3    3072   // 3*DIM

// ---------------- tf32 / mma / cp.async helpers ----------------
__device__ __forceinline__ uint32_t f2tf(float f) {
    uint32_t u;
    asm("cvt.rna.tf32.f32 %0, %1;" : "=r"(u) : "f"(f));
    return u;
}
__device__ __forceinline__ void mma_tf32(float* d, const uint32_t* a, const uint32_t* b) {
    asm("mma.sync.aligned.m16n8k8.row.col.f32.tf32.tf32.f32 "
        "{%0,%1,%2,%3},{%4,%5,%6,%7},{%8,%9},{%0,%1,%2,%3};"
        : "+f"(d[0]), "+f"(d[1]), "+f"(d[2]), "+f"(d[3])
        : "r"(a[0]), "r"(a[1]), "r"(a[2]), "r"(a[3]), "r"(b[0]), "r"(b[1]));
}
__device__ __forceinline__ void ldsm_x4(uint32_t* r, uint32_t addr) {
    asm volatile("ldmatrix.sync.aligned.m8n8.x4.shared.b16 {%0,%1,%2,%3}, [%4];"
                 : "=r"(r[0]), "=r"(r[1]), "=r"(r[2]), "=r"(r[3]) : "r"(addr));
}
__device__ __forceinline__ void cpa16(uint32_t dst, const void* src) {
    asm volatile("cp.async.cg.shared.global [%0], [%1], 16;" :: "r"(dst), "l"(src));
}
__device__ __forceinline__ void cp_commit() {
    asm volatile("cp.async.commit_group;");
}
template<int N>
__device__ __forceinline__ void cp_wait() {
    asm volatile("cp.async.wait_group %0;" :: "n"(N));
}

// ---------------- scratch (device globals) ----------------
__device__ float    g_qkv[(size_t)BATCH * SEQ * W3];     // tf32 bits [B,S,3D]
__device__ uint32_t g_ctx[(size_t)BATCH * SEQ * DIM];    // tf32 bits [B,S,D]
__device__ uint32_t g_enc_tf[(size_t)BATCH * SEQ * DIM];
__device__ uint32_t g_wattn_tf[(size_t)DIM * W3];
__device__ uint32_t g_wproj_tf[(size_t)DIM * DIM];

// ---------------- elementwise fp32 -> tf32-bits conversion ----------------
__global__ void __launch_bounds__(256) cvt_tf32_kernel(
    const float4* __restrict__ in, uint4* __restrict__ out, int n4)
{
    int i = blockIdx.x * 256 + threadIdx.x;
    if (i < n4) {
        float4 v = in[i];
        uint4 u;
        u.x = f2tf(v.x); u.y = f2tf(v.y); u.z = f2tf(v.z); u.w = f2tf(v.w);
        out[i] = u;
    }
}

// ---------------------------------------------------------------------------
// tf32 GEMM, cp.async 3-stage pipeline. Inputs are pre-converted tf32 bits.
// C = A @ B + bias;  round_out: store rna-tf32 bits instead of fp32.
// CTA 128x128x32, 256 threads, warp tile 64x32.
// ---------------------------------------------------------------------------
#define GBM 128
#define GBN 128
#define GBK 32
#define AS_STRIDE 36    // words (144B rows, 16B aligned, ldsm conflict-free)
#define BS_STRIDE 136   // words (544B rows, 16B aligned)
#define ASZ (GBM * AS_STRIDE)   // 4608 words
#define BSZ (GBK * BS_STRIDE)   // 4352 words
#define GSTAGES 3
#define GEMM_SMEM (GSTAGES * (ASZ + BSZ) * 4)   // 107520 B

__global__ void __launch_bounds__(256) tf32_gemm_pipe(
    const uint32_t* __restrict__ A, const uint32_t* __restrict__ B,
    const float* __restrict__ bias, float* __restrict__ C,
    int M, int N, int K, int round_out)
{
    extern __shared__ uint32_t sg[];
    uint32_t* As = sg;
    uint32_t* Bs = sg + GSTAGES * ASZ;

    const int tid = threadIdx.x, lane = tid & 31, warp = tid >> 5;
    const int wm = warp >> 2, wn = warp & 3, g = lane >> 2, tg = lane & 3;
    const int bm = blockIdx.y * GBM, bn = blockIdx.x * GBN;

    const uint32_t as_smem = (uint32_t)__cvta_generic_to_shared(As);
    const uint32_t bs_smem = (uint32_t)__cvta_generic_to_shared(Bs);

    float acc[4][4][4];
#pragma unroll
    for (int mt = 0; mt < 4; mt++)
#pragma unroll
        for (int nt = 0; nt < 4; nt++)
#pragma unroll
            for (int c = 0; c < 4; c++) acc[mt][nt][c] = 0.0f;

    const int a_row  = wm * 64 + (lane & 15);
    const int a_half = (lane >> 4) * 4;
    const uint32_t as_frag_base = as_smem + (uint32_t)((a_row * AS_STRIDE + a_half) * 4);

    const int nt_k = K / GBK;

    auto issue = [&](int i, int s) {
        const uint32_t* Ag = A + (size_t)bm * K + i * GBK;
#pragma unroll
        for (int t = 0; t < 4; t++) {
            int c = tid + t * 256, r = c >> 3, k16 = c & 7;
            cpa16(as_smem + (uint32_t)((s * ASZ + r * AS_STRIDE + k16 * 4) * 4),
                  Ag + (size_t)r * K + k16 * 4);
        }
        const uint32_t* Bg = B + (size_t)i * GBK * N + bn;
#pragma unroll
        for (int t = 0; t < 4; t++) {
            int c = tid + t * 256, kr = c >> 5, n16 = c & 31;
            cpa16(bs_smem + (uint32_t)((s * BSZ + kr * BS_STRIDE + n16 * 4) * 4),
                  Bg + (size_t)kr * N + n16 * 4);
        }
    };

    issue(0, 0); cp_commit();
    issue(1, 1); cp_commit();

    for (int i = 0; i < nt_k; i++) {
        cp_wait<1>();        // tile i complete (per-thread)
        __syncthreads();     // global visibility + all warps done with tile i-1
        if (i + 2 < nt_k) issue(i + 2, (i + 2) % GSTAGES);
        cp_commit();         // commit every iter (possibly empty) for uniform counting

        const int s = i % GSTAGES;
        const uint32_t a0 = as_frag_base + (uint32_t)(s * ASZ * 4);
        const uint32_t* bsS = Bs + s * BSZ;
#pragma unroll
        for (int ks = 0; ks < 4; ks++) {
            uint32_t afr[4][4];
#pragma unroll
            for (int mt = 0; mt < 4; mt++)
                ldsm_x4(afr[mt], a0 + (uint32_t)((mt * 16 * AS_STRIDE + ks * 8) * 4));
            uint32_t bfr[4][2];
#pragma unroll
            for (int nt = 0; nt < 4; nt++) {
                int n = wn * 32 + nt * 8 + g;
                bfr[nt][0] = bsS[(ks * 8 + tg) * BS_STRIDE + n];
                bfr[nt][1] = bsS[(ks * 8 + tg + 4) * BS_STRIDE + n];
            }
#pragma unroll
            for (int mt = 0; mt < 4; mt++)
#pragma unroll
                for (int nt = 0; nt < 4; nt++)
                    mma_tf32(acc[mt][nt], afr[mt], bfr[nt]);
        }
    }

    // epilogue
#pragma unroll
    for (int mt = 0; mt < 4; mt++) {
#pragma unroll
        for (int nt = 0; nt < 4; nt++) {
            int row = bm + wm * 64 + mt * 16 + g;
            int col = bn + wn * 32 + nt * 8 + 2 * tg;
            float b0 = bias[col], b1 = bias[col + 1];
            float v00 = acc[mt][nt][0] + b0, v01 = acc[mt][nt][1] + b1;
            float v10 = acc[mt][nt][2] + b0, v11 = acc[mt][nt][3] + b1;
            if (round_out) {
                v00 = __uint_as_float(f2tf(v00)); v01 = __uint_as_float(f2tf(v01));
                v10 = __uint_as_float(f2tf(v10)); v11 = __uint_as_float(f2tf(v11));
            }
            *(float2*)(C + (size_t)row * N + col)       = make_float2(v00, v01);
            *(float2*)(C + (size_t)(row + 8) * N + col) = make_float2(v10, v11);
        }
    }
}

// ---------------------------------------------------------------------------
// Tensor-core flash attention (tf32 bits in, causal), 2-stage cp.async K/V.
// Block = (b,h, 128-query tile); 8 warps x 16 query rows; 64-key tiles.
// qkv holds tf32 bits; 1/8 scale applied to S accumulators (exact).
// ctx written as tf32 bits for the proj GEMM.
// ---------------------------------------------------------------------------
#define BQ 128
#define BK 64
#define QP_STRIDE 68   // words; 272B rows, 16B aligned, ldsm conflict-free
#define V_STRIDE  72   // words; 288B rows, scalar b-frag LDS conflict-free
#define KSZ (BK * QP_STRIDE)   // 4352 words
#define VSZ (BK * V_STRIDE)    // 4608 words
#define ATTN_SMEM ((BQ * QP_STRIDE + 2 * KSZ + 2 * VSZ) * 4)   // 106496 B

__global__ void __launch_bounds__(256) attn_tc_kernel(
    const uint32_t* __restrict__ qkv, uint32_t* __restrict__ ctx)
{
    extern __shared__ uint32_t smu[];
    uint32_t* QPs = smu;                        // [128][68] Q then P
    uint32_t* Ks  = smu + BQ * QP_STRIDE;       // 2 stages [64][68]
    uint32_t* Vs  = Ks + 2 * KSZ;               // 2 stages [64][72]

    const int qt = (int)gridDim.x - 1 - (int)blockIdx.x;   // heavy tiles first
    const int bh = blockIdx.y;
    const int b = bh >> 4, h = bh & 15;
    const int qbase = qt * BQ;

    const uint32_t* base = qkv + (size_t)b * SEQ * W3;
    const int qoff = h * HS, koff = DIM + h * HS, voff = 2 * DIM + h * HS;

    const int tid = threadIdx.x, lane = tid & 31, w = tid >> 5;
    const int g = lane >> 2, tg = lane & 3;

    const uint32_t ks_smem = (uint32_t)__cvta_generic_to_shared(Ks);
    const uint32_t vs_smem = (uint32_t)__cvta_generic_to_shared(Vs);

    // ---- load Q tile (raw tf32 bits) ----
#pragma unroll
    for (int it = 0; it < 8; it++) {
        int i = tid + it * 256;
        int r = i >> 4, c4 = i & 15;
        uint4 u = *(const uint4*)(base + (size_t)(qbase + r) * W3 + qoff + c4 * 4);
        *(uint4*)&QPs[r * QP_STRIDE + c4 * 4] = u;
    }

    const int nkt = 2 * qt + 2;

    auto issue_kv = [&](int kt, int s) {
        const uint32_t* rowbase = base + (size_t)kt * BK * W3;
#pragma unroll
        for (int t = 0; t < 4; t++) {
            int c = tid + t * 256, r = c >> 4, c16 = c & 15;
            const uint32_t* row = rowbase + (size_t)r * W3;
            cpa16(ks_smem + (uint32_t)((s * KSZ + r * QP_STRIDE + c16 * 4) * 4),
                  row + koff + c16 * 4);
            cpa16(vs_smem + (uint32_t)((s * VSZ + r * V_STRIDE + c16 * 4) * 4),
                  row + voff + c16 * 4);
        }
    };

    issue_kv(0, 0); cp_commit();
    __syncthreads();   // Q visible

    // ---- Q frags -> registers ----
    const uint32_t qp_base =
        (uint32_t)__cvta_generic_to_shared(QPs) +
        (uint32_t)(((w * 16 + (lane & 15)) * QP_STRIDE + (lane >> 4) * 4) * 4);
    uint32_t qfr[8][4];
#pragma unroll
    for (int ks = 0; ks < 8; ks++)
        ldsm_x4(qfr[ks], qp_base + ks * 32);

    const uint32_t k_base =
        (uint32_t)__cvta_generic_to_shared(Ks) +
        (uint32_t)(((((lane >> 4) * 8) + (lane & 7)) * QP_STRIDE + ((lane >> 3) & 1) * 4) * 4);

    float m0 = -1e30f, m1 = -1e30f, l0 = 0.0f, l1 = 0.0f;
    float o[8][4];
#pragma unroll
    for (int nt = 0; nt < 8; nt++)
#pragma unroll
        for (int c = 0; c < 4; c++) o[nt][c] = 0.0f;

    const int qr0 = qbase + w * 16 + g;

    for (int kt = 0; kt < nkt; kt++) {
        const int kt0 = kt * BK;
        cp_wait<0>();       // my copies for tile kt done
        __syncthreads();    // everyone's copies done; all warps finished tile kt-1
        if (kt + 1 < nkt) issue_kv(kt + 1, (kt + 1) & 1);
        cp_commit();

        const int s = kt & 1;
        const uint32_t kb = k_base + (uint32_t)(s * KSZ * 4);
        const uint32_t* vsS = Vs + s * VSZ;

        // ---- S = Q K^T ----
        float sc[8][4];
#pragma unroll
        for (int nt = 0; nt < 8; nt++)
#pragma unroll
            for (int c = 0; c < 4; c++) sc[nt][c] = 0.0f;

#pragma unroll
        for (int ks = 0; ks < 8; ks++) {
#pragma unroll
            for (int ntp = 0; ntp < 4; ntp++) {
                uint32_t bb[4];
                ldsm_x4(bb, kb + (uint32_t)(ntp * 16 * QP_STRIDE * 4) + ks * 32);
                mma_tf32(sc[2 * ntp],     qfr[ks], bb);
                mma_tf32(sc[2 * ntp + 1], qfr[ks], bb + 2);
            }
        }

        // scale by 1/sqrt(64) (exact power of two)
#pragma unroll
        for (int nt = 0; nt < 8; nt++)
#pragma unroll
            for (int c = 0; c < 4; c++) sc[nt][c] *= 0.125f;

        // ---- causal mask ----
        if (kt0 + BK > qbase) {
#pragma unroll
            for (int nt = 0; nt < 8; nt++) {
                int kc = kt0 + nt * 8 + 2 * tg;
                if (qr0 < kc)         sc[nt][0] = -1e30f;
                if (qr0 < kc + 1)     sc[nt][1] = -1e30f;
                if (qr0 + 8 < kc)     sc[nt][2] = -1e30f;
                if (qr0 + 8 < kc + 1) sc[nt][3] = -1e30f;
            }
        }

        // ---- online softmax ----
        float mx0 = -1e30f, mx1 = -1e30f;
#pragma unroll
        for (int nt = 0; nt < 8; nt++) {
            mx0 = fmaxf(mx0, fmaxf(sc[nt][0], sc[nt][1]));
            mx1 = fmaxf(mx1, fmaxf(sc[nt][2], sc[nt][3]));
        }
        mx0 = fmaxf(mx0, __shfl_xor_sync(0xffffffffu, mx0, 1));
        mx0 = fmaxf(mx0, __shfl_xor_sync(0xffffffffu, mx0, 2));
        mx1 = fmaxf(mx1, __shfl_xor_sync(0xffffffffu, mx1, 1));
        mx1 = fmaxf(mx1, __shfl_xor_sync(0xffffffffu, mx1, 2));

        float mn0 = fmaxf(m0, mx0), mn1 = fmaxf(m1, mx1);
        float al0 = __expf(m0 - mn0), al1 = __expf(m1 - mn1);
        float sum0 = 0.0f, sum1 = 0.0f;

        const int pr0 = w * 16 + g;
#pragma unroll
        for (int nt = 0; nt < 8; nt++) {
            float p0 = __expf(sc[nt][0] - mn0);
            float p1 = __expf(sc[nt][1] - mn0);
            float p2 = __expf(sc[nt][2] - mn1);
            float p3 = __expf(sc[nt][3] - mn1);
            sum0 += p0 + p1;
            sum1 += p2 + p3;
            int col = nt * 8 + 2 * tg;
            QPs[pr0 * QP_STRIDE + col]           = f2tf(p0);
            QPs[pr0 * QP_STRIDE + col + 1]       = f2tf(p1);
            QPs[(pr0 + 8) * QP_STRIDE + col]     = f2tf(p2);
            QPs[(pr0 + 8) * QP_STRIDE + col + 1] = f2tf(p3);
        }
        sum0 += __shfl_xor_sync(0xffffffffu, sum0, 1);
        sum0 += __shfl_xor_sync(0xffffffffu, sum0, 2);
        sum1 += __shfl_xor_sync(0xffffffffu, sum1, 1);
        sum1 += __shfl_xor_sync(0xffffffffu, sum1, 2);

        l0 = l0 * al0 + sum0; m0 = mn0;
        l1 = l1 * al1 + sum1; m1 = mn1;

#pragma unroll
        for (int nt = 0; nt < 8; nt++) {
            o[nt][0] *= al0; o[nt][1] *= al0;
            o[nt][2] *= al1; o[nt][3] *= al1;
        }

        __syncwarp();   // own P band visible

        // ---- O += P @ V ----
#pragma unroll
        for (int ks2 = 0; ks2 < 8; ks2++) {
            uint32_t pfr[4];
            ldsm_x4(pfr, qp_base + ks2 * 32);
#pragma unroll
            for (int nt = 0; nt < 8; nt++) {
                uint32_t bb[2];
                bb[0] = vsS[(ks2 * 8 + tg) * V_STRIDE + nt * 8 + g];
                bb[1] = vsS[(ks2 * 8 + tg + 4) * V_STRIDE + nt * 8 + g];
                mma_tf32(o[nt], pfr, bb);
            }
        }
    }

    // ---- epilogue: write tf32 bits of O/l ----
    float inv0 = 1.0f / l0, inv1 = 1.0f / l1;
    uint32_t* orow0 = ctx + ((size_t)b * SEQ + qr0) * DIM + h * HS;
    uint32_t* orow1 = orow0 + (size_t)8 * DIM;
#pragma unroll
    for (int nt = 0; nt < 8; nt++) {
        int col = nt * 8 + 2 * tg;
        uint2 u0 = make_uint2(f2tf(o[nt][0] * inv0), f2tf(o[nt][1] * inv0));
        uint2 u1 = make_uint2(f2tf(o[nt][2] * inv1), f2tf(o[nt][3] * inv1));
        *(uint2*)(orow0 + col) = u0;
        *(uint2*)(orow1 + col) = u1;
    }
}

// ---------------------------------------------------------------------------
extern "C" void kernel_launch(void* const* d_in, const int* in_sizes, int n_in,
                              void* d_out, int out_size)
{
    const float* enc    = (const float*)d_in[0];
    const float* w_attn = (const float*)d_in[1];
    const float* b_attn = (const float*)d_in[2];
    const float* w_proj = (const float*)d_in[3];
    const float* b_proj = (const float*)d_in[4];
    float* out = (float*)d_out;

    float    *qkv = nullptr;
    uint32_t *ctx = nullptr, *enc_tf = nullptr, *wattn_tf = nullptr, *wproj_tf = nullptr;
    cudaGetSymbolAddress((void**)&qkv,      g_qkv);
    cudaGetSymbolAddress((void**)&ctx,      g_ctx);
    cudaGetSymbolAddress((void**)&enc_tf,   g_enc_tf);
    cudaGetSymbolAddress((void**)&wattn_tf, g_wattn_tf);
    cudaGetSymbolAddress((void**)&wproj_tf, g_wproj_tf);

    const int M = BATCH * SEQ;   // 8192

    // ---- pre-convert inputs to tf32 bits ----
    {
        int n4;
        n4 = (M * DIM) / 4;
        cvt_tf32_kernel<<<n4 / 256, 256>>>((const float4*)enc, (uint4*)enc_tf, n4);
        n4 = (DIM * W3) / 4;
        cvt_tf32_kernel<<<n4 / 256, 256>>>((const float4*)w_attn, (uint4*)wattn_tf, n4);
        n4 = (DIM * DIM) / 4;
        cvt_tf32_kernel<<<n4 / 256, 256>>>((const float4*)w_proj, (uint4*)wproj_tf, n4);
    }

    cudaFuncSetAttribute(tf32_gemm_pipe,
                         cudaFuncAttributeMaxDynamicSharedMemorySize, GEMM_SMEM);
    cudaFuncSetAttribute(attn_tc_kernel,
                         cudaFuncAttributeMaxDynamicSharedMemorySize, ATTN_SMEM);

    // ---- QKV GEMM (outputs tf32 bits) ----
    {
        dim3 grid(W3 / GBN, M / GBM);
        tf32_gemm_pipe<<<grid, 256, GEMM_SMEM>>>(
            enc_tf, wattn_tf, b_attn, qkv, M, W3, DIM, 1);
    }

    // ---- Attention (tf32 tc, cp.async K/V pipeline) ----
    {
        dim3 grid(SEQ / BQ, BATCH * HEADS);
        attn_tc_kernel<<<grid, 256, ATTN_SMEM>>>((const uint32_t*)qkv, ctx);
    }

    // ---- Output projection (fp32 out) ----
    {
        dim3 grid(DIM / GBN, M / GBM);
        tf32_gemm_pipe<<<grid, 256, GEMM_SMEM>>>(
            ctx, wproj_tf, b_proj, out, M, DIM, DIM, 0);
    }
}

// round 7
// speedup vs baseline: 6.0507x; 1.7374x over previous
#include <cuda_runtime.h>
#include <cuda_fp16.h>
#include <math.h>
#include <stdint.h>

// Problem constants: B=4, S=2048, D=1024, H=16, hs=64
#define BATCH 4
#define SEQ   2048
#define DIM   1024
#define HEADS 16
#define HS    64
#define W3    3072   // 3*DIM

// ---------------- helpers ----------------
__device__ __forceinline__ void mma_f16(float* d, const uint32_t* a,
                                        uint32_t b0, uint32_t b1) {
    asm("mma.sync.aligned.m16n8k16.row.col.f32.f16.f16.f32 "
        "{%0,%1,%2,%3},{%4,%5,%6,%7},{%8,%9},{%0,%1,%2,%3};"
        : "+f"(d[0]), "+f"(d[1]), "+f"(d[2]), "+f"(d[3])
        : "r"(a[0]), "r"(a[1]), "r"(a[2]), "r"(a[3]), "r"(b0), "r"(b1));
}
__device__ __forceinline__ void ldsm_x4(uint32_t* r, uint32_t addr) {
    asm volatile("ldmatrix.sync.aligned.m8n8.x4.shared.b16 {%0,%1,%2,%3}, [%4];"
                 : "=r"(r[0]), "=r"(r[1]), "=r"(r[2]), "=r"(r[3]) : "r"(addr));
}
__device__ __forceinline__ void ldsm_x4t(uint32_t* r, uint32_t addr) {
    asm volatile("ldmatrix.sync.aligned.m8n8.x4.trans.shared.b16 {%0,%1,%2,%3}, [%4];"
                 : "=r"(r[0]), "=r"(r[1]), "=r"(r[2]), "=r"(r[3]) : "r"(addr));
}
__device__ __forceinline__ void cpa16(uint32_t dst, const void* src) {
    asm volatile("cp.async.cg.shared.global [%0], [%1], 16;" :: "r"(dst), "l"(src));
}
__device__ __forceinline__ void cp_commit() {
    asm volatile("cp.async.commit_group;");
}
template<int N>
__device__ __forceinline__ void cp_wait() {
    asm volatile("cp.async.wait_group %0;" :: "n"(N));
}

// ---------------- scratch (device globals) ----------------
__device__ __half g_qkv[(size_t)BATCH * SEQ * W3];   // fp16 [B,S,3D]
__device__ __half g_ctx[(size_t)BATCH * SEQ * DIM];  // fp16 [B,S,D]
__device__ __half g_enc_h[(size_t)BATCH * SEQ * DIM];
__device__ __half g_wattn_h[(size_t)DIM * W3];
__device__ __half g_wproj_h[(size_t)DIM * DIM];

// ---------------- fp32 -> fp16 ----------------
__global__ void __launch_bounds__(256) cvt_f16_kernel(
    const float4* __restrict__ in, uint2* __restrict__ out, int n4)
{
    int i = blockIdx.x * 256 + threadIdx.x;
    if (i < n4) {
        float4 v = in[i];
        __half2 h0 = __float22half2_rn(make_float2(v.x, v.y));
        __half2 h1 = __float22half2_rn(make_float2(v.z, v.w));
        uint2 u;
        u.x = *(uint32_t*)&h0;
        u.y = *(uint32_t*)&h1;
        out[i] = u;
    }
}

// ---------------------------------------------------------------------------
// fp16 tensor-core GEMM: C[M,N] = A[M,K] @ B[K,N] + bias[N]
// A,B fp16 row-major. CTA 128x128x32, 3-stage cp.async, 256 thr, warp 64x32.
// half_out: store fp16 (with bias) instead of fp32.
// ---------------------------------------------------------------------------
#define GAS 40    // A smem stride (halves): 80B row, 5 x 16B (odd -> conflict-free)
#define GBS 136   // B smem stride (halves): 272B row, 17 x 16B (odd)
#define GASZ (128 * GAS)   // 5120 halves
#define GBSZ (32 * GBS)    // 4352 halves
#define GEMM_SMEM (3 * (GASZ + GBSZ) * 2)   // 56832 B

__global__ void __launch_bounds__(256) f16_gemm(
    const __half* __restrict__ A, const __half* __restrict__ B,
    const float* __restrict__ bias, void* __restrict__ Cv,
    int M, int N, int K, int half_out)
{
    extern __shared__ __half smh[];
    __half* As = smh;
    __half* Bs = smh + 3 * GASZ;

    const int tid = threadIdx.x, lane = tid & 31, w = tid >> 5;
    const int wm = w >> 2, wn = w & 3, g = lane >> 2, tg = lane & 3;
    const int bm = blockIdx.y * 128, bn = blockIdx.x * 128;

    const uint32_t as_smem = (uint32_t)__cvta_generic_to_shared(As);
    const uint32_t bs_smem = (uint32_t)__cvta_generic_to_shared(Bs);

    float acc[4][4][4];
#pragma unroll
    for (int mt = 0; mt < 4; mt++)
#pragma unroll
        for (int nt = 0; nt < 4; nt++)
#pragma unroll
            for (int c = 0; c < 4; c++) acc[mt][nt][c] = 0.0f;

    // A-fragment ldsm lane address (within a stage)
    const uint32_t a_base = as_smem +
        (uint32_t)(((wm * 64 + (lane & 15)) * GAS + (lane >> 4) * 8) * 2);
    // B-fragment (trans) lane address components
    const int b_krow = (lane & 15);            // k row within 16
    const int b_noff = (lane >> 4) * 8;        // n offset 0/8

    auto issue = [&](int i, int s) {
        const __half* Ag = A + (size_t)bm * K + i * 32;
        const uint32_t sa = as_smem + (uint32_t)(s * GASZ * 2);
#pragma unroll
        for (int t = 0; t < 2; t++) {
            int c = tid + t * 256, r = c >> 2, q = c & 3;
            cpa16(sa + (uint32_t)((r * GAS + q * 8) * 2), Ag + (size_t)r * K + q * 8);
        }
        const __half* Bg = B + (size_t)i * 32 * N + bn;
        const uint32_t sb = bs_smem + (uint32_t)(s * GBSZ * 2);
#pragma unroll
        for (int t = 0; t < 2; t++) {
            int c = tid + t * 256, r = c >> 4, u = c & 15;
            cpa16(sb + (uint32_t)((r * GBS + u * 8) * 2), Bg + (size_t)r * N + u * 8);
        }
    };

    const int nkt = K / 32;
    issue(0, 0); cp_commit();
    issue(1, 1); cp_commit();

    for (int i = 0; i < nkt; i++) {
        cp_wait<1>();
        __syncthreads();
        if (i + 2 < nkt) issue(i + 2, (i + 2) % 3);
        cp_commit();

        const int s = i % 3;
        const uint32_t a0 = a_base + (uint32_t)(s * GASZ * 2);
        const uint32_t b0s = bs_smem + (uint32_t)(s * GBSZ * 2);

#pragma unroll
        for (int ks = 0; ks < 2; ks++) {
            uint32_t afr[4][4];
#pragma unroll
            for (int mt = 0; mt < 4; mt++)
                ldsm_x4(afr[mt], a0 + (uint32_t)((mt * 16 * GAS + ks * 16) * 2));
#pragma unroll
            for (int np = 0; np < 2; np++) {
                uint32_t bb[4];
                uint32_t baddr = b0s + (uint32_t)(
                    ((ks * 16 + b_krow) * GBS + wn * 32 + np * 16 + b_noff) * 2);
                ldsm_x4t(bb, baddr);
#pragma unroll
                for (int mt = 0; mt < 4; mt++) {
                    mma_f16(acc[mt][2 * np],     afr[mt], bb[0], bb[1]);
                    mma_f16(acc[mt][2 * np + 1], afr[mt], bb[2], bb[3]);
                }
            }
        }
    }

    // ---- epilogue ----
#pragma unroll
    for (int mt = 0; mt < 4; mt++) {
#pragma unroll
        for (int nt = 0; nt < 4; nt++) {
            int row = bm + wm * 64 + mt * 16 + g;
            int col = bn + wn * 32 + nt * 8 + 2 * tg;
            float b0 = bias[col], b1 = bias[col + 1];
            float v00 = acc[mt][nt][0] + b0, v01 = acc[mt][nt][1] + b1;
            float v10 = acc[mt][nt][2] + b0, v11 = acc[mt][nt][3] + b1;
            if (half_out) {
                __half* C = (__half*)Cv;
                __half2 h0 = __float22half2_rn(make_float2(v00, v01));
                __half2 h1 = __float22half2_rn(make_float2(v10, v11));
                *(__half2*)(C + (size_t)row * N + col)       = h0;
                *(__half2*)(C + (size_t)(row + 8) * N + col) = h1;
            } else {
                float* C = (float*)Cv;
                *(float2*)(C + (size_t)row * N + col)       = make_float2(v00, v01);
                *(float2*)(C + (size_t)(row + 8) * N + col) = make_float2(v10, v11);
            }
        }
    }
}

// ---------------------------------------------------------------------------
// fp16 tensor-core flash attention (causal). BQ=128, BK=64, 8 warps x 16 rows.
// Q frags in registers; Q smem region reused for P. 2-stage cp.async K/V.
// ---------------------------------------------------------------------------
#define AST 72                 // smem stride (halves) for Q/P, K, V: 9x16B odd
#define QSZ (128 * AST)        // 9216 halves
#define KVSZ (64 * AST)        // 4608 halves per stage
#define ATTN_SMEM ((QSZ + 4 * KVSZ) * 2)   // 55296 B

__global__ void __launch_bounds__(256) attn_f16_kernel(
    const __half* __restrict__ qkv, __half* __restrict__ ctx)
{
    extern __shared__ __half smh[];
    __half* QPs = smh;                 // [128][72] Q then P
    __half* Ks  = smh + QSZ;           // 2 stages [64][72]
    __half* Vs  = Ks + 2 * KVSZ;       // 2 stages [64][72]

    const int qt = (int)gridDim.x - 1 - (int)blockIdx.x;   // heavy tiles first
    const int bh = blockIdx.y;
    const int b = bh >> 4, h = bh & 15;
    const int qbase = qt * BATCH;       // placeholder avoided; real below
    (void)qbase;
    const int qb = qt * 128;

    const __half* base = qkv + (size_t)b * SEQ * W3;
    const __half* qptr = base + h * HS;
    const __half* kptr = base + DIM + h * HS;
    const __half* vptr = base + 2 * DIM + h * HS;

    const int tid = threadIdx.x, lane = tid & 31, w = tid >> 5;
    const int g = lane >> 2, tg = lane & 3;

    const uint32_t qp_smem = (uint32_t)__cvta_generic_to_shared(QPs);
    const uint32_t k_smem  = (uint32_t)__cvta_generic_to_shared(Ks);
    const uint32_t v_smem  = (uint32_t)__cvta_generic_to_shared(Vs);

    // ---- Q tile via cp.async: 128 rows x 8 x 16B ----
#pragma unroll
    for (int t = 0; t < 4; t++) {
        int c = tid + t * 256, r = c >> 3, u = c & 7;
        cpa16(qp_smem + (uint32_t)((r * AST + u * 8) * 2),
              qptr + (size_t)(qb + r) * W3 + u * 8);
    }

    auto issue_kv = [&](int kt, int s) {
        const size_t rowb = (size_t)kt * 64 * W3;
        const uint32_t ks_ = k_smem + (uint32_t)(s * KVSZ * 2);
        const uint32_t vs_ = v_smem + (uint32_t)(s * KVSZ * 2);
#pragma unroll
        for (int t = 0; t < 2; t++) {
            int c = tid + t * 256, r = c >> 3, u = c & 7;
            cpa16(ks_ + (uint32_t)((r * AST + u * 8) * 2),
                  kptr + rowb + (size_t)r * W3 + u * 8);
            cpa16(vs_ + (uint32_t)((r * AST + u * 8) * 2),
                  vptr + rowb + (size_t)r * W3 + u * 8);
        }
    };

    issue_kv(0, 0); cp_commit();
    cp_wait<0>();
    __syncthreads();

    // ---- Q frags -> registers (4 k16 steps over hs=64) ----
    const uint32_t qp_base = qp_smem +
        (uint32_t)(((w * 16 + (lane & 15)) * AST + (lane >> 4) * 8) * 2);
    uint32_t qfr[4][4];
#pragma unroll
    for (int ks = 0; ks < 4; ks++)
        ldsm_x4(qfr[ks], qp_base + ks * 32);

    float m0 = -1e30f, m1 = -1e30f, l0 = 0.0f, l1 = 0.0f;
    float o[8][4];
#pragma unroll
    for (int nt = 0; nt < 8; nt++)
#pragma unroll
        for (int c = 0; c < 4; c++) o[nt][c] = 0.0f;

    const int nkt = 2 * qt + 2;
    const int qr0 = qb + w * 16 + g;

    // K B-frag lane address components (non-trans: key rows, c units)
    const int kb_row = ((lane >> 3) & 1) * 8 + (lane & 7);  // key row in 16
    const int kb_u   = (lane >> 4) * 8;                     // c offset 0/8
    // V B-frag (trans): k rows (=key), n units (=c)
    const int vb_row = (lane & 15);
    const int vb_u   = (lane >> 4) * 8;

    for (int kt = 0; kt < nkt; kt++) {
        const int kt0 = kt * 64;
        cp_wait<0>();
        __syncthreads();
        if (kt + 1 < nkt) issue_kv(kt + 1, (kt + 1) & 1);
        cp_commit();

        const int s = kt & 1;
        const uint32_t ksb = k_smem + (uint32_t)(s * KVSZ * 2);
        const uint32_t vsb = v_smem + (uint32_t)(s * KVSZ * 2);

        // ---- S = Q K^T ----
        float sc[8][4];
#pragma unroll
        for (int nt = 0; nt < 8; nt++)
#pragma unroll
            for (int c = 0; c < 4; c++) sc[nt][c] = 0.0f;

#pragma unroll
        for (int ks = 0; ks < 4; ks++) {
#pragma unroll
            for (int ntp = 0; ntp < 4; ntp++) {
                uint32_t bb[4];
                ldsm_x4(bb, ksb + (uint32_t)(
                    ((ntp * 16 + kb_row) * AST + ks * 16 + kb_u) * 2));
                mma_f16(sc[2 * ntp],     qfr[ks], bb[0], bb[2]);
                mma_f16(sc[2 * ntp + 1], qfr[ks], bb[1], bb[3]);
            }
        }

        // scale 1/sqrt(64)
#pragma unroll
        for (int nt = 0; nt < 8; nt++)
#pragma unroll
            for (int c = 0; c < 4; c++) sc[nt][c] *= 0.125f;

        // ---- causal mask ----
        if (kt0 + 64 > qb) {
#pragma unroll
            for (int nt = 0; nt < 8; nt++) {
                int kc = kt0 + nt * 8 + 2 * tg;
                if (qr0 < kc)         sc[nt][0] = -1e30f;
                if (qr0 < kc + 1)     sc[nt][1] = -1e30f;
                if (qr0 + 8 < kc)     sc[nt][2] = -1e30f;
                if (qr0 + 8 < kc + 1) sc[nt][3] = -1e30f;
            }
        }

        // ---- online softmax ----
        float mx0 = -1e30f, mx1 = -1e30f;
#pragma unroll
        for (int nt = 0; nt < 8; nt++) {
            mx0 = fmaxf(mx0, fmaxf(sc[nt][0], sc[nt][1]));
            mx1 = fmaxf(mx1, fmaxf(sc[nt][2], sc[nt][3]));
        }
        mx0 = fmaxf(mx0, __shfl_xor_sync(0xffffffffu, mx0, 1));
        mx0 = fmaxf(mx0, __shfl_xor_sync(0xffffffffu, mx0, 2));
        mx1 = fmaxf(mx1, __shfl_xor_sync(0xffffffffu, mx1, 1));
        mx1 = fmaxf(mx1, __shfl_xor_sync(0xffffffffu, mx1, 2));

        float mn0 = fmaxf(m0, mx0), mn1 = fmaxf(m1, mx1);
        float al0 = __expf(m0 - mn0), al1 = __expf(m1 - mn1);
        float sum0 = 0.0f, sum1 = 0.0f;

        const int pr0 = w * 16 + g;
#pragma unroll
        for (int nt = 0; nt < 8; nt++) {
            float p0 = __expf(sc[nt][0] - mn0);
            float p1 = __expf(sc[nt][1] - mn0);
            float p2 = __expf(sc[nt][2] - mn1);
            float p3 = __expf(sc[nt][3] - mn1);
            sum0 += p0 + p1;
            sum1 += p2 + p3;
            int col = nt * 8 + 2 * tg;
            *(__half2*)&QPs[pr0 * AST + col] =
                __float22half2_rn(make_float2(p0, p1));
            *(__half2*)&QPs[(pr0 + 8) * AST + col] =
                __float22half2_rn(make_float2(p2, p3));
        }
        sum0 += __shfl_xor_sync(0xffffffffu, sum0, 1);
        sum0 += __shfl_xor_sync(0xffffffffu, sum0, 2);
        sum1 += __shfl_xor_sync(0xffffffffu, sum1, 1);
        sum1 += __shfl_xor_sync(0xffffffffu, sum1, 2);

        l0 = l0 * al0 + sum0; m0 = mn0;
        l1 = l1 * al1 + sum1; m1 = mn1;

#pragma unroll
        for (int nt = 0; nt < 8; nt++) {
            o[nt][0] *= al0; o[nt][1] *= al0;
            o[nt][2] *= al1; o[nt][3] *= al1;
        }

        __syncwarp();   // own 16-row P band visible to own warp

        // ---- O += P @ V ----
#pragma unroll
        for (int ks2 = 0; ks2 < 4; ks2++) {
            uint32_t pfr[4];
            ldsm_x4(pfr, qp_base + ks2 * 32);
#pragma unroll
            for (int ct = 0; ct < 4; ct++) {
                uint32_t bb[4];
                ldsm_x4t(bb, vsb + (uint32_t)(
                    ((ks2 * 16 + vb_row) * AST + ct * 16 + vb_u) * 2));
                mma_f16(o[2 * ct],     pfr, bb[0], bb[1]);
                mma_f16(o[2 * ct + 1], pfr, bb[2], bb[3]);
            }
        }
    }

    // ---- epilogue: ctx fp16 ----
    float inv0 = 1.0f / l0, inv1 = 1.0f / l1;
    __half* orow0 = ctx + ((size_t)b * SEQ + qr0) * DIM + h * HS;
    __half* orow1 = orow0 + (size_t)8 * DIM;
#pragma unroll
    for (int nt = 0; nt < 8; nt++) {
        int col = nt * 8 + 2 * tg;
        *(__half2*)(orow0 + col) =
            __float22half2_rn(make_float2(o[nt][0] * inv0, o[nt][1] * inv0));
        *(__half2*)(orow1 + col) =
            __float22half2_rn(make_float2(o[nt][2] * inv1, o[nt][3] * inv1));
    }
}

// ---------------------------------------------------------------------------
extern "C" void kernel_launch(void* const* d_in, const int* in_sizes, int n_in,
                              void* d_out, int out_size)
{
    const float* enc    = (const float*)d_in[0];
    const float* w_attn = (const float*)d_in[1];
    const float* b_attn = (const float*)d_in[2];
    const float* w_proj = (const float*)d_in[3];
    const float* b_proj = (const float*)d_in[4];
    float* out = (float*)d_out;

    __half *qkv = nullptr, *ctx = nullptr, *enc_h = nullptr,
           *wattn_h = nullptr, *wproj_h = nullptr;
    cudaGetSymbolAddress((void**)&qkv,     g_qkv);
    cudaGetSymbolAddress((void**)&ctx,     g_ctx);
    cudaGetSymbolAddress((void**)&enc_h,   g_enc_h);
    cudaGetSymbolAddress((void**)&wattn_h, g_wattn_h);
    cudaGetSymbolAddress((void**)&wproj_h, g_wproj_h);

    const int M = BATCH * SEQ;   // 8192

    // ---- pre-convert fp32 -> fp16 ----
    {
        int n4;
        n4 = (M * DIM) / 4;
        cvt_f16_kernel<<<n4 / 256, 256>>>((const float4*)enc, (uint2*)enc_h, n4);
        n4 = (DIM * W3) / 4;
        cvt_f16_kernel<<<n4 / 256, 256>>>((const float4*)w_attn, (uint2*)wattn_h, n4);
        n4 = (DIM * DIM) / 4;
        cvt_f16_kernel<<<n4 / 256, 256>>>((const float4*)w_proj, (uint2*)wproj_h, n4);
    }

    cudaFuncSetAttribute(f16_gemm,
                         cudaFuncAttributeMaxDynamicSharedMemorySize, GEMM_SMEM);
    cudaFuncSetAttribute(attn_f16_kernel,
                         cudaFuncAttributeMaxDynamicSharedMemorySize, ATTN_SMEM);

    // ---- QKV GEMM (fp16 out) ----
    {
        dim3 grid(W3 / 128, M / 128);
        f16_gemm<<<grid, 256, GEMM_SMEM>>>(enc_h, wattn_h, b_attn, qkv,
                                           M, W3, DIM, 1);
    }

    // ---- Attention ----
    {
        dim3 grid(SEQ / 128, BATCH * HEADS);
        attn_f16_kernel<<<grid, 256, ATTN_SMEM>>>(qkv, ctx);
    }

    // ---- Output projection (fp32 out) ----
    {
        dim3 grid(DIM / 128, M / 128);
        f16_gemm<<<grid, 256, GEMM_SMEM>>>(ctx, wproj_h, b_proj, out,
                                           M, DIM, DIM, 0);
    }
}

// round 8
// speedup vs baseline: 6.4221x; 1.0614x over previous
#include <cuda_runtime.h>
#include <cuda_fp16.h>
#include <math.h>
#include <stdint.h>

// Problem constants: B=4, S=2048, D=1024, H=16, hs=64
#define BATCH 4
#define SEQ   2048
#define DIM   1024
#define HEADS 16
#define HS    64
#define W3    3072   // 3*DIM

// ---------------- helpers ----------------
__device__ __forceinline__ void mma_f16(float* d, const uint32_t* a,
                                        uint32_t b0, uint32_t b1) {
    asm("mma.sync.aligned.m16n8k16.row.col.f32.f16.f16.f32 "
        "{%0,%1,%2,%3},{%4,%5,%6,%7},{%8,%9},{%0,%1,%2,%3};"
        : "+f"(d[0]), "+f"(d[1]), "+f"(d[2]), "+f"(d[3])
        : "r"(a[0]), "r"(a[1]), "r"(a[2]), "r"(a[3]), "r"(b0), "r"(b1));
}
__device__ __forceinline__ void ldsm_x4(uint32_t* r, uint32_t addr) {
    asm volatile("ldmatrix.sync.aligned.m8n8.x4.shared.b16 {%0,%1,%2,%3}, [%4];"
                 : "=r"(r[0]), "=r"(r[1]), "=r"(r[2]), "=r"(r[3]) : "r"(addr));
}
__device__ __forceinline__ void ldsm_x4t(uint32_t* r, uint32_t addr) {
    asm volatile("ldmatrix.sync.aligned.m8n8.x4.trans.shared.b16 {%0,%1,%2,%3}, [%4];"
                 : "=r"(r[0]), "=r"(r[1]), "=r"(r[2]), "=r"(r[3]) : "r"(addr));
}
__device__ __forceinline__ void cpa16(uint32_t dst, const void* src) {
    asm volatile("cp.async.cg.shared.global [%0], [%1], 16;" :: "r"(dst), "l"(src));
}
__device__ __forceinline__ void cp_commit() {
    asm volatile("cp.async.commit_group;");
}
template<int N>
__device__ __forceinline__ void cp_wait() {
    asm volatile("cp.async.wait_group %0;" :: "n"(N));
}
__device__ __forceinline__ float fex2(float x) {   // 2^x
    float r;
    asm("ex2.approx.f32 %0, %1;" : "=f"(r) : "f"(x));
    return r;
}

// ---------------- scratch (device globals) ----------------
__device__ __half g_qkv[(size_t)BATCH * SEQ * W3];   // fp16 [B,S,3D]
__device__ __half g_ctx[(size_t)BATCH * SEQ * DIM];  // fp16 [B,S,D]
__device__ __half g_enc_h[(size_t)BATCH * SEQ * DIM];
__device__ __half g_wattn_h[(size_t)DIM * W3];
__device__ __half g_wproj_h[(size_t)DIM * DIM];

// ---------------- fp32 -> fp16 ----------------
__global__ void __launch_bounds__(256) cvt_f16_kernel(
    const float4* __restrict__ in, uint2* __restrict__ out, int n4)
{
    int i = blockIdx.x * 256 + threadIdx.x;
    if (i < n4) {
        float4 v = in[i];
        __half2 h0 = __float22half2_rn(make_float2(v.x, v.y));
        __half2 h1 = __float22half2_rn(make_float2(v.z, v.w));
        uint2 u;
        u.x = *(uint32_t*)&h0;
        u.y = *(uint32_t*)&h1;
        out[i] = u;
    }
}

// ---------------------------------------------------------------------------
// fp16 tensor-core GEMM: C[M,N] = A[M,K] @ B[K,N] + bias[N]
// A,B fp16 row-major. CTA 128x128x64, 2-stage cp.async, 256 thr, warp 64x32.
// ---------------------------------------------------------------------------
#define GAS 72    // A smem stride (halves): 9 x 16B (odd -> ldsm conflict-free)
#define GBS 136   // B smem stride (halves): 17 x 16B (odd)
#define GASZ (128 * GAS)   // 9216 halves
#define GBSZ (64 * GBS)    // 8704 halves
#define GEMM_SMEM (2 * (GASZ + GBSZ) * 2)   // 71680 B

__global__ void __launch_bounds__(256) f16_gemm(
    const __half* __restrict__ A, const __half* __restrict__ B,
    const float* __restrict__ bias, void* __restrict__ Cv,
    int M, int N, int K, int half_out)
{
    extern __shared__ __half smh[];
    __half* As = smh;
    __half* Bs = smh + 2 * GASZ;

    const int tid = threadIdx.x, lane = tid & 31, w = tid >> 5;
    const int wm = w >> 2, wn = w & 3, g = lane >> 2, tg = lane & 3;
    const int bm = blockIdx.y * 128, bn = blockIdx.x * 128;

    const uint32_t as_smem = (uint32_t)__cvta_generic_to_shared(As);
    const uint32_t bs_smem = (uint32_t)__cvta_generic_to_shared(Bs);

    float acc[4][4][4];
#pragma unroll
    for (int mt = 0; mt < 4; mt++)
#pragma unroll
        for (int nt = 0; nt < 4; nt++)
#pragma unroll
            for (int c = 0; c < 4; c++) acc[mt][nt][c] = 0.0f;

    const uint32_t a_base = as_smem +
        (uint32_t)(((wm * 64 + (lane & 15)) * GAS + (lane >> 4) * 8) * 2);
    const int b_krow = (lane & 15);
    const int b_noff = (lane >> 4) * 8;

    auto issue = [&](int i, int s) {
        const __half* Ag = A + (size_t)bm * K + i * 64;
        const uint32_t sa = as_smem + (uint32_t)(s * GASZ * 2);
#pragma unroll
        for (int t = 0; t < 4; t++) {
            int c = tid + t * 256, r = c >> 3, q = c & 7;
            cpa16(sa + (uint32_t)((r * GAS + q * 8) * 2), Ag + (size_t)r * K + q * 8);
        }
        const __half* Bg = B + (size_t)i * 64 * N + bn;
        const uint32_t sb = bs_smem + (uint32_t)(s * GBSZ * 2);
#pragma unroll
        for (int t = 0; t < 4; t++) {
            int c = tid + t * 256, r = c >> 4, u = c & 15;
            cpa16(sb + (uint32_t)((r * GBS + u * 8) * 2), Bg + (size_t)r * N + u * 8);
        }
    };

    const int nkt = K / 64;
    issue(0, 0); cp_commit();

    for (int i = 0; i < nkt; i++) {
        cp_wait<0>();       // tile i landed (issued one compute-phase ago)
        __syncthreads();    // visibility + all warps done with tile i-1's stage
        if (i + 1 < nkt) { issue(i + 1, (i + 1) & 1); cp_commit(); }

        const int s = i & 1;
        const uint32_t a0 = a_base + (uint32_t)(s * GASZ * 2);
        const uint32_t b0s = bs_smem + (uint32_t)(s * GBSZ * 2);

#pragma unroll
        for (int ks = 0; ks < 4; ks++) {
            uint32_t afr[4][4];
#pragma unroll
            for (int mt = 0; mt < 4; mt++)
                ldsm_x4(afr[mt], a0 + (uint32_t)((mt * 16 * GAS + ks * 16) * 2));
#pragma unroll
            for (int np = 0; np < 2; np++) {
                uint32_t bb[4];
                uint32_t baddr = b0s + (uint32_t)(
                    ((ks * 16 + b_krow) * GBS + wn * 32 + np * 16 + b_noff) * 2);
                ldsm_x4t(bb, baddr);
#pragma unroll
                for (int mt = 0; mt < 4; mt++) {
                    mma_f16(acc[mt][2 * np],     afr[mt], bb[0], bb[1]);
                    mma_f16(acc[mt][2 * np + 1], afr[mt], bb[2], bb[3]);
                }
            }
        }
    }

    // ---- epilogue ----
#pragma unroll
    for (int mt = 0; mt < 4; mt++) {
#pragma unroll
        for (int nt = 0; nt < 4; nt++) {
            int row = bm + wm * 64 + mt * 16 + g;
            int col = bn + wn * 32 + nt * 8 + 2 * tg;
            float b0 = bias[col], b1 = bias[col + 1];
            float v00 = acc[mt][nt][0] + b0, v01 = acc[mt][nt][1] + b1;
            float v10 = acc[mt][nt][2] + b0, v11 = acc[mt][nt][3] + b1;
            if (half_out) {
                __half* C = (__half*)Cv;
                *(__half2*)(C + (size_t)row * N + col) =
                    __float22half2_rn(make_float2(v00, v01));
                *(__half2*)(C + (size_t)(row + 8) * N + col) =
                    __float22half2_rn(make_float2(v10, v11));
            } else {
                float* C = (float*)Cv;
                *(float2*)(C + (size_t)row * N + col)       = make_float2(v00, v01);
                *(float2*)(C + (size_t)(row + 8) * N + col) = make_float2(v10, v11);
            }
        }
    }
}

// ---------------------------------------------------------------------------
// fp16 tensor-core flash attention (causal). BQ=128, BK=64, 8 warps x 16 rows.
// Q frags in registers; Q smem region reused for P. 2-stage cp.async K/V.
// Softmax in exp2 domain (log2e folded into the 1/sqrt(hs) scale).
// ---------------------------------------------------------------------------
#define AST 72                 // smem stride (halves): 9x16B odd
#define QSZ (128 * AST)
#define KVSZ (64 * AST)
#define ATTN_SMEM ((QSZ + 4 * KVSZ) * 2)   // 55296 B
#define SCALE_L2E 0.18033688f  // (1/8) * log2(e)

__global__ void __launch_bounds__(256) attn_f16_kernel(
    const __half* __restrict__ qkv, __half* __restrict__ ctx)
{
    extern __shared__ __half smh[];
    __half* QPs = smh;
    __half* Ks  = smh + QSZ;
    __half* Vs  = Ks + 2 * KVSZ;

    const int qt = (int)gridDim.x - 1 - (int)blockIdx.x;   // heavy tiles first
    const int bh = blockIdx.y;
    const int b = bh >> 4, h = bh & 15;
    const int qb = qt * 128;

    const __half* base = qkv + (size_t)b * SEQ * W3;
    const __half* qptr = base + h * HS;
    const __half* kptr = base + DIM + h * HS;
    const __half* vptr = base + 2 * DIM + h * HS;

    const int tid = threadIdx.x, lane = tid & 31, w = tid >> 5;
    const int g = lane >> 2, tg = lane & 3;

    const uint32_t qp_smem = (uint32_t)__cvta_generic_to_shared(QPs);
    const uint32_t k_smem  = (uint32_t)__cvta_generic_to_shared(Ks);
    const uint32_t v_smem  = (uint32_t)__cvta_generic_to_shared(Vs);

#pragma unroll
    for (int t = 0; t < 4; t++) {
        int c = tid + t * 256, r = c >> 3, u = c & 7;
        cpa16(qp_smem + (uint32_t)((r * AST + u * 8) * 2),
              qptr + (size_t)(qb + r) * W3 + u * 8);
    }

    auto issue_kv = [&](int kt, int s) {
        const size_t rowb = (size_t)kt * 64 * W3;
        const uint32_t ks_ = k_smem + (uint32_t)(s * KVSZ * 2);
        const uint32_t vs_ = v_smem + (uint32_t)(s * KVSZ * 2);
#pragma unroll
        for (int t = 0; t < 2; t++) {
            int c = tid + t * 256, r = c >> 3, u = c & 7;
            cpa16(ks_ + (uint32_t)((r * AST + u * 8) * 2),
                  kptr + rowb + (size_t)r * W3 + u * 8);
            cpa16(vs_ + (uint32_t)((r * AST + u * 8) * 2),
                  vptr + rowb + (size_t)r * W3 + u * 8);
        }
    };

    issue_kv(0, 0); cp_commit();
    cp_wait<0>();
    __syncthreads();

    const uint32_t qp_base = qp_smem +
        (uint32_t)(((w * 16 + (lane & 15)) * AST + (lane >> 4) * 8) * 2);
    uint32_t qfr[4][4];
#pragma unroll
    for (int ks = 0; ks < 4; ks++)
        ldsm_x4(qfr[ks], qp_base + ks * 32);

    float m0 = -1e30f, m1 = -1e30f, l0 = 0.0f, l1 = 0.0f;
    float o[8][4];
#pragma unroll
    for (int nt = 0; nt < 8; nt++)
#pragma unroll
        for (int c = 0; c < 4; c++) o[nt][c] = 0.0f;

    const int nkt = 2 * qt + 2;
    const int qr0 = qb + w * 16 + g;

    const int kb_row = ((lane >> 3) & 1) * 8 + (lane & 7);
    const int kb_u   = (lane >> 4) * 8;
    const int vb_row = (lane & 15);
    const int vb_u   = (lane >> 4) * 8;

    for (int kt = 0; kt < nkt; kt++) {
        const int kt0 = kt * 64;
        cp_wait<0>();
        __syncthreads();
        if (kt + 1 < nkt) issue_kv(kt + 1, (kt + 1) & 1);
        cp_commit();

        const int s = kt & 1;
        const uint32_t ksb = k_smem + (uint32_t)(s * KVSZ * 2);
        const uint32_t vsb = v_smem + (uint32_t)(s * KVSZ * 2);

        // ---- S = Q K^T ----
        float sc[8][4];
#pragma unroll
        for (int nt = 0; nt < 8; nt++)
#pragma unroll
            for (int c = 0; c < 4; c++) sc[nt][c] = 0.0f;

#pragma unroll
        for (int ks = 0; ks < 4; ks++) {
#pragma unroll
            for (int ntp = 0; ntp < 4; ntp++) {
                uint32_t bb[4];
                ldsm_x4(bb, ksb + (uint32_t)(
                    ((ntp * 16 + kb_row) * AST + ks * 16 + kb_u) * 2));
                mma_f16(sc[2 * ntp],     qfr[ks], bb[0], bb[2]);
                mma_f16(sc[2 * ntp + 1], qfr[ks], bb[1], bb[3]);
            }
        }

        // scale (1/sqrt(64))*log2e -> exp2 domain
#pragma unroll
        for (int nt = 0; nt < 8; nt++)
#pragma unroll
            for (int c = 0; c < 4; c++) sc[nt][c] *= SCALE_L2E;

        // ---- causal mask ----
        if (kt0 + 64 > qb) {
#pragma unroll
            for (int nt = 0; nt < 8; nt++) {
                int kc = kt0 + nt * 8 + 2 * tg;
                if (qr0 < kc)         sc[nt][0] = -1e30f;
                if (qr0 < kc + 1)     sc[nt][1] = -1e30f;
                if (qr0 + 8 < kc)     sc[nt][2] = -1e30f;
                if (qr0 + 8 < kc + 1) sc[nt][3] = -1e30f;
            }
        }

        // ---- online softmax (base-2) ----
        float mx0 = -1e30f, mx1 = -1e30f;
#pragma unroll
        for (int nt = 0; nt < 8; nt++) {
            mx0 = fmaxf(mx0, fmaxf(sc[nt][0], sc[nt][1]));
            mx1 = fmaxf(mx1, fmaxf(sc[nt][2], sc[nt][3]));
        }
        mx0 = fmaxf(mx0, __shfl_xor_sync(0xffffffffu, mx0, 1));
        mx0 = fmaxf(mx0, __shfl_xor_sync(0xffffffffu, mx0, 2));
        mx1 = fmaxf(mx1, __shfl_xor_sync(0xffffffffu, mx1, 1));
        mx1 = fmaxf(mx1, __shfl_xor_sync(0xffffffffu, mx1, 2));

        float mn0 = fmaxf(m0, mx0), mn1 = fmaxf(m1, mx1);
        float al0 = fex2(m0 - mn0), al1 = fex2(m1 - mn1);
        float sum0 = 0.0f, sum1 = 0.0f;

        const int pr0 = w * 16 + g;
#pragma unroll
        for (int nt = 0; nt < 8; nt++) {
            float p0 = fex2(sc[nt][0] - mn0);
            float p1 = fex2(sc[nt][1] - mn0);
            float p2 = fex2(sc[nt][2] - mn1);
            float p3 = fex2(sc[nt][3] - mn1);
            sum0 += p0 + p1;
            sum1 += p2 + p3;
            int col = nt * 8 + 2 * tg;
            *(__half2*)&QPs[pr0 * AST + col] =
                __float22half2_rn(make_float2(p0, p1));
            *(__half2*)&QPs[(pr0 + 8) * AST + col] =
                __float22half2_rn(make_float2(p2, p3));
        }
        sum0 += __shfl_xor_sync(0xffffffffu, sum0, 1);
        sum0 += __shfl_xor_sync(0xffffffffu, sum0, 2);
        sum1 += __shfl_xor_sync(0xffffffffu, sum1, 1);
        sum1 += __shfl_xor_sync(0xffffffffu, sum1, 2);

        l0 = l0 * al0 + sum0; m0 = mn0;
        l1 = l1 * al1 + sum1; m1 = mn1;

#pragma unroll
        for (int nt = 0; nt < 8; nt++) {
            o[nt][0] *= al0; o[nt][1] *= al0;
            o[nt][2] *= al1; o[nt][3] *= al1;
        }

        __syncwarp();   // own 16-row P band visible to own warp

        // ---- O += P @ V ----
#pragma unroll
        for (int ks2 = 0; ks2 < 4; ks2++) {
            uint32_t pfr[4];
            ldsm_x4(pfr, qp_base + ks2 * 32);
#pragma unroll
            for (int ct = 0; ct < 4; ct++) {
                uint32_t bb[4];
                ldsm_x4t(bb, vsb + (uint32_t)(
                    ((ks2 * 16 + vb_row) * AST + ct * 16 + vb_u) * 2));
                mma_f16(o[2 * ct],     pfr, bb[0], bb[1]);
                mma_f16(o[2 * ct + 1], pfr, bb[2], bb[3]);
            }
        }
    }

    // ---- epilogue: ctx fp16 ----
    float inv0 = 1.0f / l0, inv1 = 1.0f / l1;
    __half* orow0 = ctx + ((size_t)b * SEQ + qr0) * DIM + h * HS;
    __half* orow1 = orow0 + (size_t)8 * DIM;
#pragma unroll
    for (int nt = 0; nt < 8; nt++) {
        int col = nt * 8 + 2 * tg;
        *(__half2*)(orow0 + col) =
            __float22half2_rn(make_float2(o[nt][0] * inv0, o[nt][1] * inv0));
        *(__half2*)(orow1 + col) =
            __float22half2_rn(make_float2(o[nt][2] * inv1, o[nt][3] * inv1));
    }
}

// ---------------------------------------------------------------------------
extern "C" void kernel_launch(void* const* d_in, const int* in_sizes, int n_in,
                              void* d_out, int out_size)
{
    const float* enc    = (const float*)d_in[0];
    const float* w_attn = (const float*)d_in[1];
    const float* b_attn = (const float*)d_in[2];
    const float* w_proj = (const float*)d_in[3];
    const float* b_proj = (const float*)d_in[4];
    float* out = (float*)d_out;

    __half *qkv = nullptr, *ctx = nullptr, *enc_h = nullptr,
           *wattn_h = nullptr, *wproj_h = nullptr;
    cudaGetSymbolAddress((void**)&qkv,     g_qkv);
    cudaGetSymbolAddress((void**)&ctx,     g_ctx);
    cudaGetSymbolAddress((void**)&enc_h,   g_enc_h);
    cudaGetSymbolAddress((void**)&wattn_h, g_wattn_h);
    cudaGetSymbolAddress((void**)&wproj_h, g_wproj_h);

    const int M = BATCH * SEQ;   // 8192

    // ---- pre-convert fp32 -> fp16 ----
    {
        int n4;
        n4 = (M * DIM) / 4;
        cvt_f16_kernel<<<n4 / 256, 256>>>((const float4*)enc, (uint2*)enc_h, n4);
        n4 = (DIM * W3) / 4;
        cvt_f16_kernel<<<n4 / 256, 256>>>((const float4*)w_attn, (uint2*)wattn_h, n4);
        n4 = (DIM * DIM) / 4;
        cvt_f16_kernel<<<n4 / 256, 256>>>((const float4*)w_proj, (uint2*)wproj_h, n4);
    }

    cudaFuncSetAttribute(f16_gemm,
                         cudaFuncAttributeMaxDynamicSharedMemorySize, GEMM_SMEM);
    cudaFuncSetAttribute(attn_f16_kernel,
                         cudaFuncAttributeMaxDynamicSharedMemorySize, ATTN_SMEM);

    // ---- QKV GEMM (fp16 out) ----
    {
        dim3 grid(W3 / 128, M / 128);
        f16_gemm<<<grid, 256, GEMM_SMEM>>>(enc_h, wattn_h, b_attn, qkv,
                                           M, W3, DIM, 1);
    }

    // ---- Attention ----
    {
        dim3 grid(SEQ / 128, BATCH * HEADS);
        attn_f16_kernel<<<grid, 256, ATTN_SMEM>>>(qkv, ctx);
    }

    // ---- Output projection (fp32 out) ----
    {
        dim3 grid(DIM / 128, M / 128);
        f16_gemm<<<grid, 256, GEMM_SMEM>>>(ctx, wproj_h, b_proj, out,
                                           M, DIM, DIM, 0);
    }
}